// round 1
// baseline (speedup 1.0000x reference)
#include <cuda_runtime.h>
#include <math.h>

namespace {
constexpr int B_   = 64;
constexpr int NV   = 385;
constexpr int NQ   = 321;
constexpr int SS   = 256;
constexpr int NH   = 12;
constexpr int HD   = 64;
constexpr int DIM  = 768;
constexpr int QKVD = 2304;
constexpr int BH   = B_ * NH;
constexpr int TOKENS = B_ * SS;
constexpr float ATT_SCALE = 0.125f;
constexpr float EPS = 1e-6f;
}

__device__ float g_tgt[B_ * DIM];
__device__ float g_h0[(size_t)TOKENS * 1536];
__device__ float g_h1[(size_t)TOKENS * 384];
__device__ float g_h2[(size_t)TOKENS * 192];
__device__ int   g_db[TOKENS];
__device__ float g_q [(size_t)BH * NQ * HD];
__device__ float g_k [(size_t)BH * NV * HD];
__device__ float g_v [(size_t)BH * NV * HD];
__device__ float g_sc[(size_t)BH * NQ * NV];
__device__ float g_ao[(size_t)B_ * NQ * DIM];

__device__ __forceinline__ float gelu_exact(float x) {
    return 0.5f * x * (1.0f + erff(x * 0.70710678118654752440f));
}

template<int BM, int BN, int BK, int TM, int TN, bool BTRANS, int MODE>
__global__ void __launch_bounds__((BM/TM)*(BN/TN))
gemm_kernel(const float* __restrict__ A, const float* __restrict__ B,
            const float* __restrict__ bias, float* __restrict__ C,
            int M, int N, int K,
            long long aStride, long long bStride, long long cStride)
{
    constexpr int THREADS = (BM/TM)*(BN/TN);
    __shared__ float As[BK][BM];
    __shared__ float Bs[BK][BN];

    const int z  = blockIdx.z;
    const float* Ab = A + (size_t)z * aStride;
    const float* Bb = B + (size_t)z * bStride;
    float* Cb = C ? (C + (size_t)z * cStride) : nullptr;

    const int m0 = blockIdx.y * BM;
    const int n0 = blockIdx.x * BN;
    const int tid = threadIdx.x;
    const int tx = tid % (BN/TN);
    const int ty = tid / (BN/TN);
    const int tm0 = ty * TM;
    const int tn0 = tx * TN;

    float acc[TM][TN];
    #pragma unroll
    for (int i = 0; i < TM; i++)
        #pragma unroll
        for (int j = 0; j < TN; j++) acc[i][j] = 0.f;

    const bool kvec = ((K & 3) == 0);

    for (int k0 = 0; k0 < K; k0 += BK) {
        constexpr int AITER = (BM*BK/4) / THREADS;
        #pragma unroll
        for (int it = 0; it < AITER; it++) {
            int i   = tid + it * THREADS;
            int row = i / (BK/4);
            int kc  = (i % (BK/4)) * 4;
            int gm  = m0 + row, gk = k0 + kc;
            float4 v = make_float4(0.f, 0.f, 0.f, 0.f);
            if (gm < M) {
                if (kvec && gk + 3 < K) {
                    v = *(const float4*)(Ab + (size_t)gm * K + gk);
                } else {
                    float t0 = (gk   < K) ? Ab[(size_t)gm*K + gk  ] : 0.f;
                    float t1 = (gk+1 < K) ? Ab[(size_t)gm*K + gk+1] : 0.f;
                    float t2 = (gk+2 < K) ? Ab[(size_t)gm*K + gk+2] : 0.f;
                    float t3 = (gk+3 < K) ? Ab[(size_t)gm*K + gk+3] : 0.f;
                    v = make_float4(t0, t1, t2, t3);
                }
            }
            As[kc+0][row] = v.x; As[kc+1][row] = v.y;
            As[kc+2][row] = v.z; As[kc+3][row] = v.w;
        }
        if (BTRANS) {
            constexpr int BITER = (BN*BK/4) / THREADS;
            #pragma unroll
            for (int it = 0; it < BITER; it++) {
                int i   = tid + it * THREADS;
                int row = i / (BK/4);
                int kc  = (i % (BK/4)) * 4;
                int gn  = n0 + row, gk = k0 + kc;
                float4 v = make_float4(0.f, 0.f, 0.f, 0.f);
                if (gn < N) {
                    if (kvec && gk + 3 < K) {
                        v = *(const float4*)(Bb + (size_t)gn * K + gk);
                    } else {
                        float t0 = (gk   < K) ? Bb[(size_t)gn*K + gk  ] : 0.f;
                        float t1 = (gk+1 < K) ? Bb[(size_t)gn*K + gk+1] : 0.f;
                        float t2 = (gk+2 < K) ? Bb[(size_t)gn*K + gk+2] : 0.f;
                        float t3 = (gk+3 < K) ? Bb[(size_t)gn*K + gk+3] : 0.f;
                        v = make_float4(t0, t1, t2, t3);
                    }
                }
                Bs[kc+0][row] = v.x; Bs[kc+1][row] = v.y;
                Bs[kc+2][row] = v.z; Bs[kc+3][row] = v.w;
            }
        } else {
            constexpr int BITER = (BK*BN/4) / THREADS;
            #pragma unroll
            for (int it = 0; it < BITER; it++) {
                int i    = tid + it * THREADS;
                int krow = i / (BN/4);
                int nc   = (i % (BN/4)) * 4;
                int gk   = k0 + krow, gn = n0 + nc;
                float4 v = make_float4(0.f, 0.f, 0.f, 0.f);
                if (gk < K) {
                    if (gn + 3 < N) {
                        v = *(const float4*)(Bb + (size_t)gk * N + gn);
                    } else {
                        float t0 = (gn   < N) ? Bb[(size_t)gk*N + gn  ] : 0.f;
                        float t1 = (gn+1 < N) ? Bb[(size_t)gk*N + gn+1] : 0.f;
                        float t2 = (gn+2 < N) ? Bb[(size_t)gk*N + gn+2] : 0.f;
                        float t3 = (gn+3 < N) ? Bb[(size_t)gk*N + gn+3] : 0.f;
                        v = make_float4(t0, t1, t2, t3);
                    }
                }
                *(float4*)&Bs[krow][nc] = v;
            }
        }
        __syncthreads();

        #pragma unroll
        for (int kk = 0; kk < BK; kk++) {
            float a[TM], b[TN];
            #pragma unroll
            for (int i = 0; i < TM; i += 4)
                *(float4*)(a + i) = *(const float4*)(&As[kk][tm0 + i]);
            #pragma unroll
            for (int j = 0; j < TN; j += 4)
                *(float4*)(b + j) = *(const float4*)(&Bs[kk][tn0 + j]);
            #pragma unroll
            for (int i = 0; i < TM; i++)
                #pragma unroll
                for (int j = 0; j < TN; j++)
                    acc[i][j] = fmaf(a[i], b[j], acc[i][j]);
        }
        __syncthreads();
    }

    #pragma unroll
    for (int i = 0; i < TM; i++) {
        int gm = m0 + tm0 + i;
        if (gm >= M) continue;
        #pragma unroll
        for (int j = 0; j < TN; j++) {
            int gn = n0 + tn0 + j;
            if (gn >= N) continue;
            float v = acc[i][j];
            if (MODE == 0) {
                Cb[(size_t)gm * N + gn] = v + bias[gn];
            } else if (MODE == 1) {
                Cb[(size_t)gm * N + gn] = gelu_exact(v + bias[gn]);
            } else if (MODE == 2) {
                float t = v + bias[gn];
                int b  = gm / NV, nv = gm % NV;
                int typ = gn / DIM;
                int hd  = gn % DIM;
                int h = hd >> 6, d = hd & 63;
                if (typ == 1) {
                    g_k[(((size_t)b*NH + h)*NV + nv)*HD + d] = t;
                } else if (typ == 2) {
                    g_v[(((size_t)b*NH + h)*NV + nv)*HD + d] = t;
                } else {
                    int qi = (nv == 0) ? 0 : (nv >= 65 ? nv - 64 : -1);
                    if (qi >= 0)
                        g_q[(((size_t)b*NH + h)*NQ + qi)*HD + d] = t;
                }
            } else if (MODE == 3) {
                Cb[(size_t)gm * N + gn] = v * ATT_SCALE;
            } else if (MODE == 4) {
                int b = z / NH, h = z % NH;
                g_ao[((size_t)b*NQ + gm)*DIM + h*HD + gn] = v;
            }
        }
    }
}

__global__ void mean_kernel(const float* __restrict__ x) {
    int b = blockIdx.x;
    int c = threadIdx.x;
    float s = 0.f;
    #pragma unroll 8
    for (int t = 0; t < 64; t++)
        s += x[((size_t)b*NV + 65 + t)*DIM + c];
    g_tgt[b*DIM + c] = s * (1.0f/64.0f);
}

__global__ void h0_kernel(const float* __restrict__ x) {
    size_t tok = blockIdx.x;
    int b = (int)(tok >> 8), s = (int)(tok & 255);
    const float* src = x + ((size_t)b*NV + 129 + s)*DIM;
    const float* tg  = g_tgt + (size_t)b*DIM;
    float* dst = g_h0 + tok * 1536;
    for (int k = threadIdx.x; k < DIM; k += blockDim.x) {
        dst[k]       = src[k];
        dst[DIM + k] = tg[k];
    }
}

__global__ void mlp3_kernel(const float* __restrict__ w3,
                            const float* __restrict__ b3) {
    int gwarp = (blockIdx.x * blockDim.x + threadIdx.x) >> 5;
    int lane  = threadIdx.x & 31;
    if (gwarp >= TOKENS) return;
    const float* row = g_h2 + (size_t)gwarp * 192;
    float s0 = 0.f, s1 = 0.f;
    for (int k = lane; k < 192; k += 32) {
        float xv = row[k];
        s0 = fmaf(xv, w3[k],       s0);
        s1 = fmaf(xv, w3[192 + k], s1);
    }
    #pragma unroll
    for (int o = 16; o; o >>= 1) {
        s0 += __shfl_xor_sync(0xffffffffu, s0, o);
        s1 += __shfl_xor_sync(0xffffffffu, s1, o);
    }
    if (lane == 0)
        g_db[gwarp] = (s0 + b3[0] >= s1 + b3[1]) ? 1 : 0;
}

__global__ void softmax_kernel() {
    int lane = threadIdx.x & 31;
    int wid  = threadIdx.x >> 5;
    size_t row = (size_t)blockIdx.x * 8 + wid;
    if (row >= (size_t)BH * NQ) return;
    int bh = (int)(row / NQ);
    int i  = (int)(row % NQ);
    int b  = bh / NH;
    float* sp = g_sc + row * NV;
    const int* db = g_db + (size_t)b * SS;

    bool qT  = (i >= 1 && i <= 64);
    bool qP1 = (i >= 65) ? (db[i - 65] != 0) : false;

    float s[13];
    float mx = -INFINITY;
    #pragma unroll
    for (int j = 0; j < 13; j++) {
        int k = j*32 + lane;
        s[j] = (k < NV) ? sp[k] : -INFINITY;
        mx = fmaxf(mx, s[j]);
    }
    #pragma unroll
    for (int o = 16; o; o >>= 1)
        mx = fmaxf(mx, __shfl_xor_sync(0xffffffffu, mx, o));

    float e[13];
    float sum = 0.f;
    #pragma unroll
    for (int j = 0; j < 13; j++) {
        int k = j*32 + lane;
        if (k < NV) {
            bool kT  = (k >= 1 && k <= 128);
            bool kP1 = (k >= 129) ? (db[k - 129] != 0) : false;
            float m = ((qT && kP1) || (qP1 && kT)) ? 0.f : 1.f;
            e[j] = expf(s[j] - mx) * m;
        } else e[j] = 0.f;
        sum += e[j];
    }
    #pragma unroll
    for (int o = 16; o; o >>= 1)
        sum += __shfl_xor_sync(0xffffffffu, sum, o);

    float inv = 1.0f / (sum + EPS);
    const float c = EPS / (float)NQ;
    #pragma unroll
    for (int j = 0; j < 13; j++) {
        int k = j*32 + lane;
        if (k < NV) sp[k] = (e[j] + c) * inv;
    }
}

extern "C" void kernel_launch(void* const* d_in, const int* in_sizes, int n_in,
                              void* d_out, int out_size) {
    const float* x      = (const float*)d_in[0];
    const float* qkv_w  = (const float*)d_in[2];
    const float* qkv_b  = (const float*)d_in[3];
    const float* proj_w = (const float*)d_in[4];
    const float* proj_b = (const float*)d_in[5];
    const float* dp1_w  = (const float*)d_in[6];
    const float* dp1_b  = (const float*)d_in[7];
    const float* dp2_w  = (const float*)d_in[8];
    const float* dp2_b  = (const float*)d_in[9];
    const float* dp3_w  = (const float*)d_in[10];
    const float* dp3_b  = (const float*)d_in[11];
    float* out = (float*)d_out;

    float *p_h0, *p_h1, *p_h2, *p_q, *p_k, *p_v, *p_sc, *p_ao;
    cudaGetSymbolAddress((void**)&p_h0, g_h0);
    cudaGetSymbolAddress((void**)&p_h1, g_h1);
    cudaGetSymbolAddress((void**)&p_h2, g_h2);
    cudaGetSymbolAddress((void**)&p_q,  g_q);
    cudaGetSymbolAddress((void**)&p_k,  g_k);
    cudaGetSymbolAddress((void**)&p_v,  g_v);
    cudaGetSymbolAddress((void**)&p_sc, g_sc);
    cudaGetSymbolAddress((void**)&p_ao, g_ao);

    auto cdiv = [](int a, int b) { return (a + b - 1) / b; };

    mean_kernel<<<B_, DIM>>>(x);
    h0_kernel<<<TOKENS, 256>>>(x);
    gemm_kernel<128,128,16,8,8,true,1>
        <<<dim3(cdiv(384,128), cdiv(TOKENS,128), 1), 256>>>(
            p_h0, dp1_w, dp1_b, p_h1, TOKENS, 384, 1536, 0, 0, 0);
    gemm_kernel<128,128,16,8,8,true,1>
        <<<dim3(cdiv(192,128), cdiv(TOKENS,128), 1), 256>>>(
            p_h1, dp2_w, dp2_b, p_h2, TOKENS, 192, 384, 0, 0, 0);
    mlp3_kernel<<<cdiv(TOKENS*32, 256), 256>>>(dp3_w, dp3_b);
    gemm_kernel<128,128,16,8,8,true,2>
        <<<dim3(cdiv(QKVD,128), cdiv(B_*NV,128), 1), 256>>>(
            x, qkv_w, qkv_b, nullptr, B_*NV, QKVD, DIM, 0, 0, 0);
    gemm_kernel<128,128,16,8,8,true,3>
        <<<dim3(cdiv(NV,128), cdiv(NQ,128), BH), 256>>>(
            p_q, p_k, nullptr, p_sc, NQ, NV, HD,
            (long long)NQ*HD, (long long)NV*HD, (long long)NQ*NV);
    softmax_kernel<<<cdiv(BH*NQ, 8), 256>>>();
    gemm_kernel<128,64,16,8,4,false,4>
        <<<dim3(cdiv(HD,64), cdiv(NQ,128), BH), 256>>>(
            p_sc, p_v, nullptr, nullptr, NQ, HD, NV,
            (long long)NQ*NV, (long long)NV*HD, 0);
    gemm_kernel<128,128,16,8,8,true,0>
        <<<dim3(cdiv(DIM,128), cdiv(B_*NQ,128), 1), 256>>>(
            p_ao, proj_w, proj_b, out, B_*NQ, DIM, DIM, 0, 0, 0);
}

// round 2
// speedup vs baseline: 1.2818x; 1.2818x over previous
#include <cuda_runtime.h>
#include <math.h>
#include <stdint.h>

namespace {
constexpr int B_   = 64;
constexpr int NV   = 385;
constexpr int NQ   = 321;
constexpr int SS   = 256;
constexpr int NH   = 12;
constexpr int HD   = 64;
constexpr int DIM  = 768;
constexpr int QKVD = 2304;
constexpr int BH   = B_ * NH;
constexpr int TOKENS = B_ * SS;
constexpr float ATT_SCALE = 0.125f;
constexpr float EPS = 1e-6f;
}

__device__ float g_tgt[B_ * DIM];
__device__ float g_h0[(size_t)TOKENS * 1536];
__device__ float g_h1[(size_t)TOKENS * 384];
__device__ float g_h2[(size_t)TOKENS * 192];
__device__ int   g_db[TOKENS];
__device__ float g_q [(size_t)BH * NQ * HD];
__device__ float g_k [(size_t)BH * NV * HD];
__device__ float g_v [(size_t)BH * NV * HD];
__device__ float g_sc[(size_t)BH * NQ * NV];
__device__ float g_ao[(size_t)B_ * NQ * DIM];

__device__ __forceinline__ float gelu_exact(float x) {
    return 0.5f * x * (1.0f + erff(x * 0.70710678118654752440f));
}

__device__ __forceinline__ float to_tf32(float x) {
    uint32_t r;
    asm("cvt.rna.tf32.f32 %0, %1;" : "=r"(r) : "f"(x));
    return __uint_as_float(r);
}

__device__ __forceinline__ void mma_tf32(float c[4], const uint32_t a[4],
                                         const uint32_t b[2]) {
    asm volatile(
        "mma.sync.aligned.m16n8k8.row.col.f32.tf32.tf32.f32 "
        "{%0,%1,%2,%3}, {%4,%5,%6,%7}, {%8,%9}, {%0,%1,%2,%3};"
        : "+f"(c[0]), "+f"(c[1]), "+f"(c[2]), "+f"(c[3])
        : "r"(a[0]), "r"(a[1]), "r"(a[2]), "r"(a[3]),
          "r"(b[0]), "r"(b[1]));
}

// ---------------------------------------------------------------------------
// TF32 tensor-core GEMM. 256 threads, 8 warps in 4(M) x 2(N) grid.
// As[k][m] / Bs[k][n] smem layout -> row.col mma fragments.
// MODE: 0 bias+store, 2 qkv scatter, 3 *SCALE store, 4 PV->g_ao scatter
// ---------------------------------------------------------------------------
template<int BM, int BN, int BK, bool BTRANS, int MODE>
__global__ void __launch_bounds__(256, 2)
tc_gemm(const float* __restrict__ A, const float* __restrict__ B,
        const float* __restrict__ bias, float* __restrict__ C,
        int M, int N, int K,
        long long aStride, long long bStride, long long cStride)
{
    constexpr int THREADS = 256;
    constexpr int WTM = BM / 4;           // 32
    constexpr int WTN = BN / 2;           // 64 or 32
    constexpr int MT = WTM / 16;          // 2
    constexpr int NT = WTN / 8;           // 8 or 4
    constexpr int ASTR = BM + 1;
    constexpr int BSTR = BTRANS ? (BN + 1) : (BN + 4);

    __shared__ float As[BK][ASTR];
    __shared__ float Bs[BK][BSTR];

    const int z  = blockIdx.z;
    const float* Ab = A + (size_t)z * aStride;
    const float* Bb = B + (size_t)z * bStride;
    float* Cb = C ? (C + (size_t)z * cStride) : nullptr;

    const int m0 = blockIdx.y * BM;
    const int n0 = blockIdx.x * BN;
    const int tid  = threadIdx.x;
    const int lane = tid & 31;
    const int w    = tid >> 5;
    const int wm = w >> 1, wn = w & 1;
    const int g  = lane >> 2, tg = lane & 3;
    const int m0w = wm * WTM, n0w = wn * WTN;

    float acc[MT][NT][4];
    #pragma unroll
    for (int i = 0; i < MT; i++)
        #pragma unroll
        for (int j = 0; j < NT; j++)
            #pragma unroll
            for (int r = 0; r < 4; r++) acc[i][j][r] = 0.f;

    const bool kvec = ((K & 3) == 0);

    for (int k0 = 0; k0 < K; k0 += BK) {
        // ---- A tile (BM x BK) -> As[k][m], tf32-rounded
        constexpr int AITER = (BM * BK / 4) / THREADS;
        #pragma unroll
        for (int it = 0; it < AITER; it++) {
            int i   = tid + it * THREADS;
            int row = i / (BK / 4);
            int kc  = (i % (BK / 4)) * 4;
            int gm  = m0 + row, gk = k0 + kc;
            float4 v = make_float4(0.f, 0.f, 0.f, 0.f);
            if (gm < M) {
                if (kvec && gk + 3 < K) {
                    v = *(const float4*)(Ab + (size_t)gm * K + gk);
                } else {
                    v.x = (gk   < K) ? Ab[(size_t)gm*K + gk  ] : 0.f;
                    v.y = (gk+1 < K) ? Ab[(size_t)gm*K + gk+1] : 0.f;
                    v.z = (gk+2 < K) ? Ab[(size_t)gm*K + gk+2] : 0.f;
                    v.w = (gk+3 < K) ? Ab[(size_t)gm*K + gk+3] : 0.f;
                }
            }
            As[kc+0][row] = to_tf32(v.x); As[kc+1][row] = to_tf32(v.y);
            As[kc+2][row] = to_tf32(v.z); As[kc+3][row] = to_tf32(v.w);
        }
        // ---- B tile
        if (BTRANS) {
            constexpr int BITER = (BN * BK / 4) / THREADS;
            #pragma unroll
            for (int it = 0; it < BITER; it++) {
                int i   = tid + it * THREADS;
                int row = i / (BK / 4);
                int kc  = (i % (BK / 4)) * 4;
                int gn  = n0 + row, gk = k0 + kc;
                float4 v = make_float4(0.f, 0.f, 0.f, 0.f);
                if (gn < N) {
                    if (kvec && gk + 3 < K) {
                        v = *(const float4*)(Bb + (size_t)gn * K + gk);
                    } else {
                        v.x = (gk   < K) ? Bb[(size_t)gn*K + gk  ] : 0.f;
                        v.y = (gk+1 < K) ? Bb[(size_t)gn*K + gk+1] : 0.f;
                        v.z = (gk+2 < K) ? Bb[(size_t)gn*K + gk+2] : 0.f;
                        v.w = (gk+3 < K) ? Bb[(size_t)gn*K + gk+3] : 0.f;
                    }
                }
                Bs[kc+0][row] = to_tf32(v.x); Bs[kc+1][row] = to_tf32(v.y);
                Bs[kc+2][row] = to_tf32(v.z); Bs[kc+3][row] = to_tf32(v.w);
            }
        } else {
            constexpr int BITER = (BK * BN / 4) / THREADS;
            #pragma unroll
            for (int it = 0; it < BITER; it++) {
                int i    = tid + it * THREADS;
                int krow = i / (BN / 4);
                int nc   = (i % (BN / 4)) * 4;
                int gk   = k0 + krow, gn = n0 + nc;
                float4 v = make_float4(0.f, 0.f, 0.f, 0.f);
                if (gk < K) {
                    if (gn + 3 < N) {
                        v = *(const float4*)(Bb + (size_t)gk * N + gn);
                    } else {
                        v.x = (gn   < N) ? Bb[(size_t)gk*N + gn  ] : 0.f;
                        v.y = (gn+1 < N) ? Bb[(size_t)gk*N + gn+1] : 0.f;
                        v.z = (gn+2 < N) ? Bb[(size_t)gk*N + gn+2] : 0.f;
                        v.w = (gn+3 < N) ? Bb[(size_t)gk*N + gn+3] : 0.f;
                    }
                }
                v.x = to_tf32(v.x); v.y = to_tf32(v.y);
                v.z = to_tf32(v.z); v.w = to_tf32(v.w);
                *(float4*)&Bs[krow][nc] = v;
            }
        }
        __syncthreads();

        #pragma unroll
        for (int kk = 0; kk < BK; kk += 8) {
            uint32_t a[MT][4], b[NT][2];
            #pragma unroll
            for (int i = 0; i < MT; i++) {
                a[i][0] = __float_as_uint(As[kk+tg  ][m0w + i*16 + g    ]);
                a[i][1] = __float_as_uint(As[kk+tg  ][m0w + i*16 + g + 8]);
                a[i][2] = __float_as_uint(As[kk+tg+4][m0w + i*16 + g    ]);
                a[i][3] = __float_as_uint(As[kk+tg+4][m0w + i*16 + g + 8]);
            }
            #pragma unroll
            for (int j = 0; j < NT; j++) {
                b[j][0] = __float_as_uint(Bs[kk+tg  ][n0w + j*8 + g]);
                b[j][1] = __float_as_uint(Bs[kk+tg+4][n0w + j*8 + g]);
            }
            #pragma unroll
            for (int i = 0; i < MT; i++)
                #pragma unroll
                for (int j = 0; j < NT; j++)
                    mma_tf32(acc[i][j], a[i], b[j]);
        }
        __syncthreads();
    }

    // ---- epilogue
    #pragma unroll
    for (int i = 0; i < MT; i++) {
        #pragma unroll
        for (int j = 0; j < NT; j++) {
            #pragma unroll
            for (int r = 0; r < 4; r++) {
                int gm = m0 + m0w + i*16 + g + ((r & 2) ? 8 : 0);
                int gn = n0 + n0w + j*8 + tg*2 + (r & 1);
                if (gm >= M || gn >= N) continue;
                float v = acc[i][j][r];
                if (MODE == 0) {
                    Cb[(size_t)gm * N + gn] = v + bias[gn];
                } else if (MODE == 2) {
                    float t = v + bias[gn];
                    int b  = gm / NV, nv = gm % NV;
                    int typ = gn / DIM;
                    int hd  = gn % DIM;
                    int h = hd >> 6, d = hd & 63;
                    if (typ == 1) {
                        g_k[(((size_t)b*NH + h)*NV + nv)*HD + d] = t;
                    } else if (typ == 2) {
                        g_v[(((size_t)b*NH + h)*NV + nv)*HD + d] = t;
                    } else {
                        int qi = (nv == 0) ? 0 : (nv >= 65 ? nv - 64 : -1);
                        if (qi >= 0)
                            g_q[(((size_t)b*NH + h)*NQ + qi)*HD + d] = t;
                    }
                } else if (MODE == 3) {
                    Cb[(size_t)gm * N + gn] = v * ATT_SCALE;
                } else if (MODE == 4) {
                    int b = z / NH, h = z % NH;
                    g_ao[((size_t)b*NQ + gm)*DIM + h*HD + gn] = v;
                }
            }
        }
    }
}

// ---------------------------------------------------------------------------
// FP32 FFMA GEMM (exact) — used for the MLP decision path only.
// ---------------------------------------------------------------------------
template<int BM, int BN, int BK, int TM, int TN>
__global__ void __launch_bounds__((BM/TM)*(BN/TN))
gemm_gelu_kernel(const float* __restrict__ A, const float* __restrict__ B,
                 const float* __restrict__ bias, float* __restrict__ C,
                 int M, int N, int K)
{
    constexpr int THREADS = (BM/TM)*(BN/TN);
    __shared__ float As[BK][BM];
    __shared__ float Bs[BK][BN];

    const int m0 = blockIdx.y * BM;
    const int n0 = blockIdx.x * BN;
    const int tid = threadIdx.x;
    const int tx = tid % (BN/TN);
    const int ty = tid / (BN/TN);
    const int tm0 = ty * TM;
    const int tn0 = tx * TN;

    float acc[TM][TN];
    #pragma unroll
    for (int i = 0; i < TM; i++)
        #pragma unroll
        for (int j = 0; j < TN; j++) acc[i][j] = 0.f;

    for (int k0 = 0; k0 < K; k0 += BK) {
        constexpr int AITER = (BM*BK/4) / THREADS;
        #pragma unroll
        for (int it = 0; it < AITER; it++) {
            int i   = tid + it * THREADS;
            int row = i / (BK/4);
            int kc  = (i % (BK/4)) * 4;
            int gm  = m0 + row, gk = k0 + kc;
            float4 v = make_float4(0.f, 0.f, 0.f, 0.f);
            if (gm < M && gk + 3 < K)
                v = *(const float4*)(A + (size_t)gm * K + gk);
            As[kc+0][row] = v.x; As[kc+1][row] = v.y;
            As[kc+2][row] = v.z; As[kc+3][row] = v.w;
        }
        constexpr int BITER = (BN*BK/4) / THREADS;
        #pragma unroll
        for (int it = 0; it < BITER; it++) {
            int i   = tid + it * THREADS;
            int row = i / (BK/4);
            int kc  = (i % (BK/4)) * 4;
            int gn  = n0 + row, gk = k0 + kc;
            float4 v = make_float4(0.f, 0.f, 0.f, 0.f);
            if (gn < N && gk + 3 < K)
                v = *(const float4*)(B + (size_t)gn * K + gk);
            Bs[kc+0][row] = v.x; Bs[kc+1][row] = v.y;
            Bs[kc+2][row] = v.z; Bs[kc+3][row] = v.w;
        }
        __syncthreads();

        #pragma unroll
        for (int kk = 0; kk < BK; kk++) {
            float a[TM], b[TN];
            #pragma unroll
            for (int i = 0; i < TM; i += 4)
                *(float4*)(a + i) = *(const float4*)(&As[kk][tm0 + i]);
            #pragma unroll
            for (int j = 0; j < TN; j += 4)
                *(float4*)(b + j) = *(const float4*)(&Bs[kk][tn0 + j]);
            #pragma unroll
            for (int i = 0; i < TM; i++)
                #pragma unroll
                for (int j = 0; j < TN; j++)
                    acc[i][j] = fmaf(a[i], b[j], acc[i][j]);
        }
        __syncthreads();
    }

    #pragma unroll
    for (int i = 0; i < TM; i++) {
        int gm = m0 + tm0 + i;
        if (gm >= M) continue;
        #pragma unroll
        for (int j = 0; j < TN; j++) {
            int gn = n0 + tn0 + j;
            if (gn >= N) continue;
            C[(size_t)gm * N + gn] = gelu_exact(acc[i][j] + bias[gn]);
        }
    }
}

__global__ void mean_kernel(const float* __restrict__ x) {
    int b = blockIdx.x;
    int c = threadIdx.x;
    float s = 0.f;
    #pragma unroll 8
    for (int t = 0; t < 64; t++)
        s += x[((size_t)b*NV + 65 + t)*DIM + c];
    g_tgt[b*DIM + c] = s * (1.0f/64.0f);
}

__global__ void h0_kernel(const float* __restrict__ x) {
    size_t tok = blockIdx.x;
    int b = (int)(tok >> 8), s = (int)(tok & 255);
    const float* src = x + ((size_t)b*NV + 129 + s)*DIM;
    const float* tg  = g_tgt + (size_t)b*DIM;
    float* dst = g_h0 + tok * 1536;
    for (int k = threadIdx.x; k < DIM; k += blockDim.x) {
        dst[k]       = src[k];
        dst[DIM + k] = tg[k];
    }
}

__global__ void mlp3_kernel(const float* __restrict__ w3,
                            const float* __restrict__ b3) {
    int gwarp = (blockIdx.x * blockDim.x + threadIdx.x) >> 5;
    int lane  = threadIdx.x & 31;
    if (gwarp >= TOKENS) return;
    const float* row = g_h2 + (size_t)gwarp * 192;
    float s0 = 0.f, s1 = 0.f;
    for (int k = lane; k < 192; k += 32) {
        float xv = row[k];
        s0 = fmaf(xv, w3[k],       s0);
        s1 = fmaf(xv, w3[192 + k], s1);
    }
    #pragma unroll
    for (int o = 16; o; o >>= 1) {
        s0 += __shfl_xor_sync(0xffffffffu, s0, o);
        s1 += __shfl_xor_sync(0xffffffffu, s1, o);
    }
    if (lane == 0)
        g_db[gwarp] = (s0 + b3[0] >= s1 + b3[1]) ? 1 : 0;
}

__global__ void softmax_kernel() {
    int lane = threadIdx.x & 31;
    int wid  = threadIdx.x >> 5;
    size_t row = (size_t)blockIdx.x * 8 + wid;
    if (row >= (size_t)BH * NQ) return;
    int bh = (int)(row / NQ);
    int i  = (int)(row % NQ);
    int b  = bh / NH;
    float* sp = g_sc + row * NV;
    const int* db = g_db + (size_t)b * SS;

    bool qT  = (i >= 1 && i <= 64);
    bool qP1 = (i >= 65) ? (db[i - 65] != 0) : false;

    float s[13];
    float mx = -INFINITY;
    #pragma unroll
    for (int j = 0; j < 13; j++) {
        int k = j*32 + lane;
        s[j] = (k < NV) ? sp[k] : -INFINITY;
        mx = fmaxf(mx, s[j]);
    }
    #pragma unroll
    for (int o = 16; o; o >>= 1)
        mx = fmaxf(mx, __shfl_xor_sync(0xffffffffu, mx, o));

    float e[13];
    float sum = 0.f;
    #pragma unroll
    for (int j = 0; j < 13; j++) {
        int k = j*32 + lane;
        if (k < NV) {
            bool kT  = (k >= 1 && k <= 128);
            bool kP1 = (k >= 129) ? (db[k - 129] != 0) : false;
            float m = ((qT && kP1) || (qP1 && kT)) ? 0.f : 1.f;
            e[j] = expf(s[j] - mx) * m;
        } else e[j] = 0.f;
        sum += e[j];
    }
    #pragma unroll
    for (int o = 16; o; o >>= 1)
        sum += __shfl_xor_sync(0xffffffffu, sum, o);

    float inv = 1.0f / (sum + EPS);
    const float c = EPS / (float)NQ;
    #pragma unroll
    for (int j = 0; j < 13; j++) {
        int k = j*32 + lane;
        if (k < NV) sp[k] = (e[j] + c) * inv;
    }
}

extern "C" void kernel_launch(void* const* d_in, const int* in_sizes, int n_in,
                              void* d_out, int out_size) {
    const float* x      = (const float*)d_in[0];
    const float* qkv_w  = (const float*)d_in[2];
    const float* qkv_b  = (const float*)d_in[3];
    const float* proj_w = (const float*)d_in[4];
    const float* proj_b = (const float*)d_in[5];
    const float* dp1_w  = (const float*)d_in[6];
    const float* dp1_b  = (const float*)d_in[7];
    const float* dp2_w  = (const float*)d_in[8];
    const float* dp2_b  = (const float*)d_in[9];
    const float* dp3_w  = (const float*)d_in[10];
    const float* dp3_b  = (const float*)d_in[11];
    float* out = (float*)d_out;

    float *p_h0, *p_h1, *p_h2, *p_q, *p_k, *p_v, *p_sc, *p_ao;
    cudaGetSymbolAddress((void**)&p_h0, g_h0);
    cudaGetSymbolAddress((void**)&p_h1, g_h1);
    cudaGetSymbolAddress((void**)&p_h2, g_h2);
    cudaGetSymbolAddress((void**)&p_q,  g_q);
    cudaGetSymbolAddress((void**)&p_k,  g_k);
    cudaGetSymbolAddress((void**)&p_v,  g_v);
    cudaGetSymbolAddress((void**)&p_sc, g_sc);
    cudaGetSymbolAddress((void**)&p_ao, g_ao);

    auto cdiv = [](int a, int b) { return (a + b - 1) / b; };

    // decision path (exact fp32 — feeds argmax, must match reference bits)
    mean_kernel<<<B_, DIM>>>(x);
    h0_kernel<<<TOKENS, 256>>>(x);
    gemm_gelu_kernel<128,128,16,8,8>
        <<<dim3(cdiv(384,128), cdiv(TOKENS,128)), 256>>>(
            p_h0, dp1_w, dp1_b, p_h1, TOKENS, 384, 1536);
    gemm_gelu_kernel<128,128,16,8,8>
        <<<dim3(cdiv(192,128), cdiv(TOKENS,128)), 256>>>(
            p_h1, dp2_w, dp2_b, p_h2, TOKENS, 192, 384);
    mlp3_kernel<<<cdiv(TOKENS*32, 256), 256>>>(dp3_w, dp3_b);

    // heavy GEMMs on tensor cores (tf32)
    tc_gemm<128,128,32,true,2>
        <<<dim3(cdiv(QKVD,128), cdiv(B_*NV,128), 1), 256>>>(
            x, qkv_w, qkv_b, nullptr, B_*NV, QKVD, DIM, 0, 0, 0);
    tc_gemm<128,128,32,true,3>
        <<<dim3(cdiv(NV,128), cdiv(NQ,128), BH), 256>>>(
            p_q, p_k, nullptr, p_sc, NQ, NV, HD,
            (long long)NQ*HD, (long long)NV*HD, (long long)NQ*NV);
    softmax_kernel<<<cdiv(BH*NQ, 8), 256>>>();
    tc_gemm<128,64,32,false,4>
        <<<dim3(cdiv(HD,64), cdiv(NQ,128), BH), 256>>>(
            p_sc, p_v, nullptr, nullptr, NQ, HD, NV,
            (long long)NQ*NV, (long long)NV*HD, 0);
    tc_gemm<128,128,32,true,0>
        <<<dim3(cdiv(DIM,128), cdiv(B_*NQ,128), 1), 256>>>(
            p_ao, proj_w, proj_b, out, B_*NQ, DIM, DIM, 0, 0, 0);
}

// round 3
// speedup vs baseline: 1.7905x; 1.3969x over previous
#include <cuda_runtime.h>
#include <math.h>
#include <stdint.h>

namespace {
constexpr int B_   = 64;
constexpr int NV   = 385;
constexpr int NQ   = 321;
constexpr int SS   = 256;
constexpr int NH   = 12;
constexpr int HD   = 64;
constexpr int DIM  = 768;
constexpr int QKVD = 2304;
constexpr int BH   = B_ * NH;
constexpr int TOKENS = B_ * SS;
constexpr float ATT_SCALE = 0.125f;
constexpr float EPS = 1e-6f;
}

__device__ float g_tgt[B_ * DIM];
__device__ float g_h1[(size_t)TOKENS * 384];
__device__ float g_h2[(size_t)TOKENS * 192];
__device__ int   g_db[TOKENS];
__device__ float g_q [(size_t)BH * NQ * HD];
__device__ float g_k [(size_t)BH * NV * HD];
__device__ float g_v [(size_t)BH * NV * HD];
__device__ float g_vsum[BH * HD];
__device__ float g_ao[(size_t)B_ * NQ * DIM];

__device__ __forceinline__ float gelu_exact(float x) {
    return 0.5f * x * (1.0f + erff(x * 0.70710678118654752440f));
}

__device__ __forceinline__ float to_tf32(float x) {
    uint32_t r;
    asm("cvt.rna.tf32.f32 %0, %1;" : "=r"(r) : "f"(x));
    return __uint_as_float(r);
}

__device__ __forceinline__ void mma_tf32(float c[4], const uint32_t a[4],
                                         const uint32_t b[2]) {
    asm volatile(
        "mma.sync.aligned.m16n8k8.row.col.f32.tf32.tf32.f32 "
        "{%0,%1,%2,%3}, {%4,%5,%6,%7}, {%8,%9}, {%0,%1,%2,%3};"
        : "+f"(c[0]), "+f"(c[1]), "+f"(c[2]), "+f"(c[3])
        : "r"(a[0]), "r"(a[1]), "r"(a[2]), "r"(a[3]),
          "r"(b[0]), "r"(b[1]));
}

// ---------------------------------------------------------------------------
// TF32 tensor-core GEMM (single precision pass). B is (N,K) row-major.
// MODE: 0 bias+store, 2 qkv scatter
// ---------------------------------------------------------------------------
template<int BM, int BN, int BK, int MODE>
__global__ void __launch_bounds__(256, 2)
tc_gemm(const float* __restrict__ A, const float* __restrict__ B,
        const float* __restrict__ bias, float* __restrict__ C,
        int M, int N, int K)
{
    constexpr int THREADS = 256;
    constexpr int WTM = BM / 4;
    constexpr int WTN = BN / 2;
    constexpr int MT = WTM / 16;
    constexpr int NT = WTN / 8;
    constexpr int ASTR = BM + 1;
    constexpr int BSTR = BN + 1;

    __shared__ float As[BK][ASTR];
    __shared__ float Bs[BK][BSTR];

    const int m0 = blockIdx.y * BM;
    const int n0 = blockIdx.x * BN;
    const int tid  = threadIdx.x;
    const int lane = tid & 31;
    const int w    = tid >> 5;
    const int wm = w >> 1, wn = w & 1;
    const int g  = lane >> 2, tg = lane & 3;
    const int m0w = wm * WTM, n0w = wn * WTN;

    float acc[MT][NT][4];
    #pragma unroll
    for (int i = 0; i < MT; i++)
        #pragma unroll
        for (int j = 0; j < NT; j++)
            #pragma unroll
            for (int r = 0; r < 4; r++) acc[i][j][r] = 0.f;

    for (int k0 = 0; k0 < K; k0 += BK) {
        constexpr int AITER = (BM * BK / 4) / THREADS;
        #pragma unroll
        for (int it = 0; it < AITER; it++) {
            int i   = tid + it * THREADS;
            int row = i / (BK / 4);
            int kc  = (i % (BK / 4)) * 4;
            int gm  = m0 + row, gk = k0 + kc;
            float4 v = make_float4(0.f, 0.f, 0.f, 0.f);
            if (gm < M && gk + 3 < K)
                v = *(const float4*)(A + (size_t)gm * K + gk);
            As[kc+0][row] = to_tf32(v.x); As[kc+1][row] = to_tf32(v.y);
            As[kc+2][row] = to_tf32(v.z); As[kc+3][row] = to_tf32(v.w);
        }
        constexpr int BITER = (BN * BK / 4) / THREADS;
        #pragma unroll
        for (int it = 0; it < BITER; it++) {
            int i   = tid + it * THREADS;
            int row = i / (BK / 4);
            int kc  = (i % (BK / 4)) * 4;
            int gn  = n0 + row, gk = k0 + kc;
            float4 v = make_float4(0.f, 0.f, 0.f, 0.f);
            if (gn < N && gk + 3 < K)
                v = *(const float4*)(B + (size_t)gn * K + gk);
            Bs[kc+0][row] = to_tf32(v.x); Bs[kc+1][row] = to_tf32(v.y);
            Bs[kc+2][row] = to_tf32(v.z); Bs[kc+3][row] = to_tf32(v.w);
        }
        __syncthreads();

        #pragma unroll
        for (int kk = 0; kk < BK; kk += 8) {
            uint32_t a[MT][4], b[NT][2];
            #pragma unroll
            for (int i = 0; i < MT; i++) {
                a[i][0] = __float_as_uint(As[kk+tg  ][m0w + i*16 + g    ]);
                a[i][1] = __float_as_uint(As[kk+tg  ][m0w + i*16 + g + 8]);
                a[i][2] = __float_as_uint(As[kk+tg+4][m0w + i*16 + g    ]);
                a[i][3] = __float_as_uint(As[kk+tg+4][m0w + i*16 + g + 8]);
            }
            #pragma unroll
            for (int j = 0; j < NT; j++) {
                b[j][0] = __float_as_uint(Bs[kk+tg  ][n0w + j*8 + g]);
                b[j][1] = __float_as_uint(Bs[kk+tg+4][n0w + j*8 + g]);
            }
            #pragma unroll
            for (int i = 0; i < MT; i++)
                #pragma unroll
                for (int j = 0; j < NT; j++)
                    mma_tf32(acc[i][j], a[i], b[j]);
        }
        __syncthreads();
    }

    #pragma unroll
    for (int i = 0; i < MT; i++) {
        #pragma unroll
        for (int j = 0; j < NT; j++) {
            #pragma unroll
            for (int r = 0; r < 4; r++) {
                int gm = m0 + m0w + i*16 + g + ((r & 2) ? 8 : 0);
                int gn = n0 + n0w + j*8 + tg*2 + (r & 1);
                if (gm >= M || gn >= N) continue;
                float v = acc[i][j][r];
                if (MODE == 0) {
                    C[(size_t)gm * N + gn] = v + bias[gn];
                } else {
                    float t = v + bias[gn];
                    int b  = gm / NV, nv = gm % NV;
                    int typ = gn / DIM;
                    int hd  = gn % DIM;
                    int h = hd >> 6, d = hd & 63;
                    if (typ == 1) {
                        g_k[(((size_t)b*NH + h)*NV + nv)*HD + d] = t;
                    } else if (typ == 2) {
                        g_v[(((size_t)b*NH + h)*NV + nv)*HD + d] = t;
                    } else {
                        int qi = (nv == 0) ? 0 : (nv >= 65 ? nv - 64 : -1);
                        if (qi >= 0)
                            g_q[(((size_t)b*NH + h)*NQ + qi)*HD + d] = t;
                    }
                }
            }
        }
    }
}

// ---------------------------------------------------------------------------
// 3xTF32 GEMM + GELU (fp32-accurate via hi/lo split) for the decision MLP.
// AMODE 0: A given pointer (M,K).  AMODE 1: A = concat(x_search, tgt_rep).
// B is (N,K) row-major (weights).
// ---------------------------------------------------------------------------
template<int AMODE>
__global__ void __launch_bounds__(256)
tc_gemm3x_gelu(const float* __restrict__ A, const float* __restrict__ x,
               const float* __restrict__ B, const float* __restrict__ bias,
               float* __restrict__ C, int M, int N, int K)
{
    constexpr int BM = 128, BN = 128, BK = 16;
    constexpr int WTM = 32, WTN = 64;
    constexpr int MT = 2, NT = 8;

    __shared__ float Ah[BK][BM+1], Al[BK][BM+1];
    __shared__ float Bh[BK][BN+1], Bl[BK][BN+1];

    const int m0 = blockIdx.y * BM;
    const int n0 = blockIdx.x * BN;
    const int tid  = threadIdx.x;
    const int lane = tid & 31;
    const int w    = tid >> 5;
    const int wm = w >> 1, wn = w & 1;
    const int g  = lane >> 2, tg = lane & 3;
    const int m0w = wm * WTM, n0w = wn * WTN;

    float acc[MT][NT][4];
    #pragma unroll
    for (int i = 0; i < MT; i++)
        #pragma unroll
        for (int j = 0; j < NT; j++)
            #pragma unroll
            for (int r = 0; r < 4; r++) acc[i][j][r] = 0.f;

    for (int k0 = 0; k0 < K; k0 += BK) {
        #pragma unroll
        for (int it = 0; it < 2; it++) {
            int i   = tid + it * 256;
            int row = i / (BK / 4);
            int kc  = (i % (BK / 4)) * 4;
            int gm  = m0 + row, gk = k0 + kc;
            float4 v;
            if (AMODE == 1) {
                int bx = gm >> 8, sx = gm & 255;
                if (gk < DIM)
                    v = *(const float4*)(x + ((size_t)bx*NV + 129 + sx)*DIM + gk);
                else
                    v = *(const float4*)(g_tgt + (size_t)bx*DIM + gk - DIM);
            } else {
                v = *(const float4*)(A + (size_t)gm * K + gk);
            }
            float hx = to_tf32(v.x), hy = to_tf32(v.y),
                  hz = to_tf32(v.z), hw = to_tf32(v.w);
            Ah[kc+0][row] = hx; Al[kc+0][row] = to_tf32(v.x - hx);
            Ah[kc+1][row] = hy; Al[kc+1][row] = to_tf32(v.y - hy);
            Ah[kc+2][row] = hz; Al[kc+2][row] = to_tf32(v.z - hz);
            Ah[kc+3][row] = hw; Al[kc+3][row] = to_tf32(v.w - hw);
        }
        #pragma unroll
        for (int it = 0; it < 2; it++) {
            int i   = tid + it * 256;
            int row = i / (BK / 4);
            int kc  = (i % (BK / 4)) * 4;
            int gn  = n0 + row, gk = k0 + kc;
            float4 v = make_float4(0.f, 0.f, 0.f, 0.f);
            if (gn < N)
                v = *(const float4*)(B + (size_t)gn * K + gk);
            float hx = to_tf32(v.x), hy = to_tf32(v.y),
                  hz = to_tf32(v.z), hw = to_tf32(v.w);
            Bh[kc+0][row] = hx; Bl[kc+0][row] = to_tf32(v.x - hx);
            Bh[kc+1][row] = hy; Bl[kc+1][row] = to_tf32(v.y - hy);
            Bh[kc+2][row] = hz; Bl[kc+2][row] = to_tf32(v.z - hz);
            Bh[kc+3][row] = hw; Bl[kc+3][row] = to_tf32(v.w - hw);
        }
        __syncthreads();

        #pragma unroll
        for (int kk = 0; kk < BK; kk += 8) {
            uint32_t ah[MT][4], al[MT][4];
            #pragma unroll
            for (int i = 0; i < MT; i++) {
                ah[i][0] = __float_as_uint(Ah[kk+tg  ][m0w + i*16 + g    ]);
                ah[i][1] = __float_as_uint(Ah[kk+tg  ][m0w + i*16 + g + 8]);
                ah[i][2] = __float_as_uint(Ah[kk+tg+4][m0w + i*16 + g    ]);
                ah[i][3] = __float_as_uint(Ah[kk+tg+4][m0w + i*16 + g + 8]);
                al[i][0] = __float_as_uint(Al[kk+tg  ][m0w + i*16 + g    ]);
                al[i][1] = __float_as_uint(Al[kk+tg  ][m0w + i*16 + g + 8]);
                al[i][2] = __float_as_uint(Al[kk+tg+4][m0w + i*16 + g    ]);
                al[i][3] = __float_as_uint(Al[kk+tg+4][m0w + i*16 + g + 8]);
            }
            #pragma unroll
            for (int j = 0; j < NT; j++) {
                uint32_t bh2[2] = {
                    __float_as_uint(Bh[kk+tg  ][n0w + j*8 + g]),
                    __float_as_uint(Bh[kk+tg+4][n0w + j*8 + g])};
                uint32_t bl2[2] = {
                    __float_as_uint(Bl[kk+tg  ][n0w + j*8 + g]),
                    __float_as_uint(Bl[kk+tg+4][n0w + j*8 + g])};
                #pragma unroll
                for (int i = 0; i < MT; i++) {
                    mma_tf32(acc[i][j], ah[i], bl2);
                    mma_tf32(acc[i][j], al[i], bh2);
                    mma_tf32(acc[i][j], ah[i], bh2);
                }
            }
        }
        __syncthreads();
    }

    #pragma unroll
    for (int i = 0; i < MT; i++) {
        #pragma unroll
        for (int j = 0; j < NT; j++) {
            #pragma unroll
            for (int r = 0; r < 4; r++) {
                int gm = m0 + m0w + i*16 + g + ((r & 2) ? 8 : 0);
                int gn = n0 + n0w + j*8 + tg*2 + (r & 1);
                if (gm >= M || gn >= N) continue;
                C[(size_t)gm * N + gn] = gelu_exact(acc[i][j][r] + bias[gn]);
            }
        }
    }
}

// ---------------------------------------------------------------------------
// Flash attention: QK^T -> online masked softmax -> PV, fused per 128-q tile.
// ---------------------------------------------------------------------------
namespace {
constexpr int BQ = 128, BKV = 64;
}

struct FlashSmem {
    float Qs[HD][BQ + 4];
    float Ks[HD][BKV + 4];
    float Vs[BKV][HD + 4];
    float Ps[BKV][BQ + 4];
    int   km[BKV];
};

__global__ void __launch_bounds__(256)
flash_kernel() {
    extern __shared__ char raw_smem[];
    FlashSmem& S = *reinterpret_cast<FlashSmem*>(raw_smem);

    const int bh = blockIdx.y;
    const int b  = bh / NH, h = bh % NH;
    const int q0 = blockIdx.x * BQ;
    const int tid  = threadIdx.x;
    const int lane = tid & 31;
    const int w    = tid >> 5;
    const int g  = lane >> 2, tg = lane & 3;
    const int mw = w * 16;
    const int* db = g_db + (size_t)b * SS;

    // Q tile (pre-scaled by ATT_SCALE, exact pow2 -> tf32 rounding unchanged)
    for (int idx = tid; idx < BQ * HD; idx += 256) {
        int q = idx >> 6, d = idx & 63;
        int gq = q0 + q;
        float v = (gq < NQ) ? g_q[((size_t)bh*NQ + gq)*HD + d] * ATT_SCALE : 0.f;
        S.Qs[d][q] = to_tf32(v);
    }

    // query categories for this thread's two rows
    const int r0 = q0 + mw + g, r1 = r0 + 8;
    const bool qT0 = (r0 >= 1 && r0 <= 64);
    const bool qT1 = (r1 >= 1 && r1 <= 64);
    const bool qP0 = (r0 >= 65 && r0 < NQ) ? (db[r0 - 65] != 0) : false;
    const bool qP1 = (r1 >= 65 && r1 < NQ) ? (db[r1 - 65] != 0) : false;

    float m0 = -INFINITY, m1 = -INFINITY, l0 = 0.f, l1 = 0.f;
    float accO[8][4];
    #pragma unroll
    for (int j = 0; j < 8; j++)
        #pragma unroll
        for (int r = 0; r < 4; r++) accO[j][r] = 0.f;

    for (int kt = 0; kt < 7; kt++) {
        __syncthreads();
        const int kbase = kt * BKV;
        for (int idx = tid; idx < BKV * HD; idx += 256) {
            int kv = idx >> 6, d = idx & 63;
            int k = kbase + kv;
            float kvl = 0.f, vvl = 0.f;
            if (k < NV) {
                kvl = g_k[((size_t)bh*NV + k)*HD + d];
                vvl = g_v[((size_t)bh*NV + k)*HD + d];
            }
            S.Ks[d][kv] = to_tf32(kvl);
            S.Vs[kv][d] = to_tf32(vvl);
        }
        if (tid < BKV) {
            int k = kbase + tid;
            int fl = 0;
            if (k < NV) {
                fl = 4;
                if (k >= 1 && k <= 128) fl |= 1;
                if (k >= 129 && db[k - 129] != 0) fl |= 2;
            }
            S.km[tid] = fl;
        }
        __syncthreads();

        // S = Q K^T  (scaled scores)
        float sacc[8][4];
        #pragma unroll
        for (int j = 0; j < 8; j++)
            #pragma unroll
            for (int r = 0; r < 4; r++) sacc[j][r] = 0.f;

        #pragma unroll
        for (int kk = 0; kk < HD; kk += 8) {
            uint32_t a[4];
            a[0] = __float_as_uint(S.Qs[kk+tg  ][mw + g    ]);
            a[1] = __float_as_uint(S.Qs[kk+tg  ][mw + g + 8]);
            a[2] = __float_as_uint(S.Qs[kk+tg+4][mw + g    ]);
            a[3] = __float_as_uint(S.Qs[kk+tg+4][mw + g + 8]);
            #pragma unroll
            for (int j = 0; j < 8; j++) {
                uint32_t b2[2] = {
                    __float_as_uint(S.Ks[kk+tg  ][j*8 + g]),
                    __float_as_uint(S.Ks[kk+tg+4][j*8 + g])};
                mma_tf32(sacc[j], a, b2);
            }
        }

        // online softmax update
        int fA[8], fB[8];
        float tm0 = -INFINITY, tm1 = -INFINITY;
        #pragma unroll
        for (int j = 0; j < 8; j++) {
            int kvA = j*8 + 2*tg;
            fA[j] = S.km[kvA];
            fB[j] = S.km[kvA + 1];
            if (fA[j] & 4) { tm0 = fmaxf(tm0, sacc[j][0]); tm1 = fmaxf(tm1, sacc[j][2]); }
            if (fB[j] & 4) { tm0 = fmaxf(tm0, sacc[j][1]); tm1 = fmaxf(tm1, sacc[j][3]); }
        }
        #pragma unroll
        for (int o = 1; o <= 2; o <<= 1) {
            tm0 = fmaxf(tm0, __shfl_xor_sync(0xffffffffu, tm0, o));
            tm1 = fmaxf(tm1, __shfl_xor_sync(0xffffffffu, tm1, o));
        }
        float nm0 = fmaxf(m0, tm0), nm1 = fmaxf(m1, tm1);
        float f0 = __expf(m0 - nm0), f1 = __expf(m1 - nm1);

        float rs0 = 0.f, rs1 = 0.f;
        #pragma unroll
        for (int j = 0; j < 8; j++) {
            bool mA0 = (fA[j] & 4) && !((qT0 && (fA[j] & 2)) || (qP0 && (fA[j] & 1)));
            bool mB0 = (fB[j] & 4) && !((qT0 && (fB[j] & 2)) || (qP0 && (fB[j] & 1)));
            bool mA1 = (fA[j] & 4) && !((qT1 && (fA[j] & 2)) || (qP1 && (fA[j] & 1)));
            bool mB1 = (fB[j] & 4) && !((qT1 && (fB[j] & 2)) || (qP1 && (fB[j] & 1)));
            float e00 = mA0 ? __expf(sacc[j][0] - nm0) : 0.f;
            float e01 = mB0 ? __expf(sacc[j][1] - nm0) : 0.f;
            float e10 = mA1 ? __expf(sacc[j][2] - nm1) : 0.f;
            float e11 = mB1 ? __expf(sacc[j][3] - nm1) : 0.f;
            rs0 += e00 + e01;
            rs1 += e10 + e11;
            int kvA = j*8 + 2*tg;
            S.Ps[kvA    ][mw + g    ] = to_tf32(e00);
            S.Ps[kvA + 1][mw + g    ] = to_tf32(e01);
            S.Ps[kvA    ][mw + g + 8] = to_tf32(e10);
            S.Ps[kvA + 1][mw + g + 8] = to_tf32(e11);
        }
        #pragma unroll
        for (int o = 1; o <= 2; o <<= 1) {
            rs0 += __shfl_xor_sync(0xffffffffu, rs0, o);
            rs1 += __shfl_xor_sync(0xffffffffu, rs1, o);
        }
        l0 = l0 * f0 + rs0;
        l1 = l1 * f1 + rs1;
        #pragma unroll
        for (int j = 0; j < 8; j++) {
            accO[j][0] *= f0; accO[j][1] *= f0;
            accO[j][2] *= f1; accO[j][3] *= f1;
        }
        m0 = nm0; m1 = nm1;
        __syncwarp();

        // O += P V  (warp reads only its own P columns)
        #pragma unroll
        for (int kk = 0; kk < BKV; kk += 8) {
            uint32_t a[4];
            a[0] = __float_as_uint(S.Ps[kk+tg  ][mw + g    ]);
            a[1] = __float_as_uint(S.Ps[kk+tg  ][mw + g + 8]);
            a[2] = __float_as_uint(S.Ps[kk+tg+4][mw + g    ]);
            a[3] = __float_as_uint(S.Ps[kk+tg+4][mw + g + 8]);
            #pragma unroll
            for (int j = 0; j < 8; j++) {
                uint32_t b2[2] = {
                    __float_as_uint(S.Vs[kk+tg  ][j*8 + g]),
                    __float_as_uint(S.Vs[kk+tg+4][j*8 + g])};
                mma_tf32(accO[j], a, b2);
            }
        }
    }

    // epilogue: out = (O + (eps/NQ) * colsum(V)) / (l + eps)
    const float inv0 = 1.f / (l0 + EPS);
    const float inv1 = 1.f / (l1 + EPS);
    const float c = EPS / (float)NQ;
    #pragma unroll
    for (int j = 0; j < 8; j++) {
        #pragma unroll
        for (int r = 0; r < 4; r++) {
            int d = j*8 + 2*tg + (r & 1);
            int q = q0 + mw + g + ((r & 2) ? 8 : 0);
            if (q >= NQ) continue;
            float vs = g_vsum[bh * HD + d];
            float val = (accO[j][r] + c * vs) * ((r & 2) ? inv1 : inv0);
            g_ao[((size_t)b*NQ + q)*DIM + h*HD + d] = val;
        }
    }
}

// ---------------------------------------------------------------------------
// small kernels
// ---------------------------------------------------------------------------
__global__ void mean_kernel(const float* __restrict__ x) {
    int b = blockIdx.x;
    int c = threadIdx.x;
    float s = 0.f;
    #pragma unroll 8
    for (int t = 0; t < 64; t++)
        s += x[((size_t)b*NV + 65 + t)*DIM + c];
    g_tgt[b*DIM + c] = s * (1.0f/64.0f);
}

__global__ void mlp3_kernel(const float* __restrict__ w3,
                            const float* __restrict__ b3) {
    int gwarp = (blockIdx.x * blockDim.x + threadIdx.x) >> 5;
    int lane  = threadIdx.x & 31;
    if (gwarp >= TOKENS) return;
    const float* row = g_h2 + (size_t)gwarp * 192;
    float s0 = 0.f, s1 = 0.f;
    for (int k = lane; k < 192; k += 32) {
        float xv = row[k];
        s0 = fmaf(xv, w3[k],       s0);
        s1 = fmaf(xv, w3[192 + k], s1);
    }
    #pragma unroll
    for (int o = 16; o; o >>= 1) {
        s0 += __shfl_xor_sync(0xffffffffu, s0, o);
        s1 += __shfl_xor_sync(0xffffffffu, s1, o);
    }
    if (lane == 0)
        g_db[gwarp] = (s0 + b3[0] >= s1 + b3[1]) ? 1 : 0;
}

__global__ void vsum_kernel() {
    int bh = blockIdx.x;
    int d  = threadIdx.x;
    float s = 0.f;
    for (int k = 0; k < NV; k++)
        s += g_v[((size_t)bh*NV + k)*HD + d];
    g_vsum[bh*HD + d] = s;
}

// ---------------------------------------------------------------------------
extern "C" void kernel_launch(void* const* d_in, const int* in_sizes, int n_in,
                              void* d_out, int out_size) {
    const float* x      = (const float*)d_in[0];
    const float* qkv_w  = (const float*)d_in[2];
    const float* qkv_b  = (const float*)d_in[3];
    const float* proj_w = (const float*)d_in[4];
    const float* proj_b = (const float*)d_in[5];
    const float* dp1_w  = (const float*)d_in[6];
    const float* dp1_b  = (const float*)d_in[7];
    const float* dp2_w  = (const float*)d_in[8];
    const float* dp2_b  = (const float*)d_in[9];
    const float* dp3_w  = (const float*)d_in[10];
    const float* dp3_b  = (const float*)d_in[11];
    float* out = (float*)d_out;

    float *p_h1, *p_h2, *p_ao;
    cudaGetSymbolAddress((void**)&p_h1, g_h1);
    cudaGetSymbolAddress((void**)&p_h2, g_h2);
    cudaGetSymbolAddress((void**)&p_ao, g_ao);

    auto cdiv = [](int a, int b) { return (a + b - 1) / b; };

    // decision path (3xTF32 ~ fp32-accurate)
    mean_kernel<<<B_, DIM>>>(x);
    tc_gemm3x_gelu<1><<<dim3(cdiv(384,128), cdiv(TOKENS,128)), 256>>>(
        nullptr, x, dp1_w, dp1_b, p_h1, TOKENS, 384, 1536);
    tc_gemm3x_gelu<0><<<dim3(cdiv(192,128), cdiv(TOKENS,128)), 256>>>(
        p_h1, nullptr, dp2_w, dp2_b, p_h2, TOKENS, 192, 384);
    mlp3_kernel<<<cdiv(TOKENS*32, 256), 256>>>(dp3_w, dp3_b);

    // QKV projection + head scatter
    tc_gemm<128,128,32,2><<<dim3(cdiv(QKVD,128), cdiv(B_*NV,128)), 256>>>(
        x, qkv_w, qkv_b, nullptr, B_*NV, QKVD, DIM);

    // V column sums (for eps/NQ term)
    vsum_kernel<<<BH, HD>>>();

    // fused attention
    constexpr size_t FLASH_SMEM = sizeof(FlashSmem);
    cudaFuncSetAttribute(flash_kernel,
                         cudaFuncAttributeMaxDynamicSharedMemorySize,
                         (int)FLASH_SMEM);
    flash_kernel<<<dim3(cdiv(NQ, BQ), BH), 256, FLASH_SMEM>>>();

    // output projection
    tc_gemm<128,128,32,0><<<dim3(cdiv(DIM,128), cdiv(B_*NQ,128)), 256>>>(
        p_ao, proj_w, proj_b, out, B_*NQ, DIM, DIM);
}

// round 4
// speedup vs baseline: 1.8310x; 1.0226x over previous
#include <cuda_runtime.h>
#include <math.h>
#include <stdint.h>

namespace {
constexpr int B_   = 64;
constexpr int NV   = 385;
constexpr int NQ   = 321;
constexpr int SS   = 256;
constexpr int NH   = 12;
constexpr int HD   = 64;
constexpr int DIM  = 768;
constexpr int QKVD = 2304;
constexpr int BH   = B_ * NH;
constexpr int TOKENS = B_ * SS;
constexpr float ATT_SCALE = 0.125f;
constexpr float EPS = 1e-6f;
}

__device__ float g_tgt[B_ * DIM];
__device__ float g_tb[B_ * 384];
__device__ float g_h1[(size_t)TOKENS * 384];
__device__ float g_h2[(size_t)TOKENS * 192];
__device__ int   g_db[TOKENS];
__device__ float g_q [(size_t)BH * NQ * HD];
__device__ float g_k [(size_t)BH * NV * HD];
__device__ float g_v [(size_t)BH * NV * HD];
__device__ float g_vsum[BH * HD];
__device__ float g_ao[(size_t)B_ * NQ * DIM];

__device__ __forceinline__ float gelu_exact(float x) {
    return 0.5f * x * (1.0f + erff(x * 0.70710678118654752440f));
}

__device__ __forceinline__ float to_tf32(float x) {
    uint32_t r;
    asm("cvt.rna.tf32.f32 %0, %1;" : "=r"(r) : "f"(x));
    return __uint_as_float(r);
}

__device__ __forceinline__ void mma_tf32(float c[4], const uint32_t a[4],
                                         const uint32_t b[2]) {
    asm volatile(
        "mma.sync.aligned.m16n8k8.row.col.f32.tf32.tf32.f32 "
        "{%0,%1,%2,%3}, {%4,%5,%6,%7}, {%8,%9}, {%0,%1,%2,%3};"
        : "+f"(c[0]), "+f"(c[1]), "+f"(c[2]), "+f"(c[3])
        : "r"(a[0]), "r"(a[1]), "r"(a[2]), "r"(a[3]),
          "r"(b[0]), "r"(b[1]));
}

// ---------------------------------------------------------------------------
// TF32 tensor-core GEMM, register-prefetch double-buffered.
// B is (N,K) row-major. K must be a multiple of 16.
// MODE: 0 bias+store, 2 qkv scatter
// ---------------------------------------------------------------------------
template<int MODE>
__global__ void __launch_bounds__(256)
tc_gemm(const float* __restrict__ A, const float* __restrict__ B,
        const float* __restrict__ bias, float* __restrict__ C,
        int M, int N, int K)
{
    constexpr int BM = 128, BN = 128, BK = 16;
    constexpr int MT = 2, NT = 8;

    __shared__ float As[BK][BM + 1];
    __shared__ float Bs[BK][BN + 1];

    const int m0 = blockIdx.y * BM;
    const int n0 = blockIdx.x * BN;
    const int tid  = threadIdx.x;
    const int lane = tid & 31;
    const int w    = tid >> 5;
    const int wm = w >> 1, wn = w & 1;
    const int g  = lane >> 2, tg = lane & 3;
    const int m0w = wm * 32, n0w = wn * 64;

    // per-thread load coordinates (fixed across tiles)
    const int lrow = tid >> 2;            // 0..63  (+64 per it)
    const int lkc  = (tid & 3) * 4;       // 0,4,8,12

    float acc[MT][NT][4];
    #pragma unroll
    for (int i = 0; i < MT; i++)
        #pragma unroll
        for (int j = 0; j < NT; j++)
            #pragma unroll
            for (int r = 0; r < 4; r++) acc[i][j][r] = 0.f;

    float4 rA[2], rB[2];

    auto load_tiles = [&](int k0) {
        #pragma unroll
        for (int it = 0; it < 2; it++) {
            int row = lrow + it * 64;
            int gm  = m0 + row, gk = k0 + lkc;
            rA[it] = (gm < M) ? *(const float4*)(A + (size_t)gm * K + gk)
                              : make_float4(0.f, 0.f, 0.f, 0.f);
            int gn = n0 + row;
            rB[it] = (gn < N) ? *(const float4*)(B + (size_t)gn * K + gk)
                              : make_float4(0.f, 0.f, 0.f, 0.f);
        }
    };
    auto store_tiles = [&]() {
        #pragma unroll
        for (int it = 0; it < 2; it++) {
            int row = lrow + it * 64;
            As[lkc+0][row] = to_tf32(rA[it].x);
            As[lkc+1][row] = to_tf32(rA[it].y);
            As[lkc+2][row] = to_tf32(rA[it].z);
            As[lkc+3][row] = to_tf32(rA[it].w);
            Bs[lkc+0][row] = to_tf32(rB[it].x);
            Bs[lkc+1][row] = to_tf32(rB[it].y);
            Bs[lkc+2][row] = to_tf32(rB[it].z);
            Bs[lkc+3][row] = to_tf32(rB[it].w);
        }
    };

    load_tiles(0);
    for (int k0 = 0; k0 < K; k0 += BK) {
        store_tiles();
        __syncthreads();
        if (k0 + BK < K) load_tiles(k0 + BK);

        #pragma unroll
        for (int kk = 0; kk < BK; kk += 8) {
            uint32_t a[MT][4], b[NT][2];
            #pragma unroll
            for (int i = 0; i < MT; i++) {
                a[i][0] = __float_as_uint(As[kk+tg  ][m0w + i*16 + g    ]);
                a[i][1] = __float_as_uint(As[kk+tg  ][m0w + i*16 + g + 8]);
                a[i][2] = __float_as_uint(As[kk+tg+4][m0w + i*16 + g    ]);
                a[i][3] = __float_as_uint(As[kk+tg+4][m0w + i*16 + g + 8]);
            }
            #pragma unroll
            for (int j = 0; j < NT; j++) {
                b[j][0] = __float_as_uint(Bs[kk+tg  ][n0w + j*8 + g]);
                b[j][1] = __float_as_uint(Bs[kk+tg+4][n0w + j*8 + g]);
            }
            #pragma unroll
            for (int i = 0; i < MT; i++)
                #pragma unroll
                for (int j = 0; j < NT; j++)
                    mma_tf32(acc[i][j], a[i], b[j]);
        }
        __syncthreads();
    }

    #pragma unroll
    for (int i = 0; i < MT; i++) {
        #pragma unroll
        for (int j = 0; j < NT; j++) {
            #pragma unroll
            for (int r = 0; r < 4; r++) {
                int gm = m0 + m0w + i*16 + g + ((r & 2) ? 8 : 0);
                int gn = n0 + n0w + j*8 + tg*2 + (r & 1);
                if (gm >= M || gn >= N) continue;
                float v = acc[i][j][r];
                if (MODE == 0) {
                    C[(size_t)gm * N + gn] = v + bias[gn];
                } else {
                    float t = v + bias[gn];
                    int bb = gm / NV, nv = gm % NV;
                    int typ = gn / DIM;
                    int hd  = gn % DIM;
                    int h = hd >> 6, d = hd & 63;
                    if (typ == 1) {
                        g_k[(((size_t)bb*NH + h)*NV + nv)*HD + d] = t;
                    } else if (typ == 2) {
                        g_v[(((size_t)bb*NH + h)*NV + nv)*HD + d] = t;
                    } else {
                        int qi = (nv == 0) ? 0 : (nv >= 65 ? nv - 64 : -1);
                        if (qi >= 0)
                            g_q[(((size_t)bb*NH + h)*NQ + qi)*HD + d] = t;
                    }
                }
            }
        }
    }
}

// ---------------------------------------------------------------------------
// 3xTF32 GEMM + GELU (fp32-accurate hi/lo split), register-prefetch pipelined.
// AMODE 0: A = given pointer (M,K).     bias[gn]
// AMODE 1: A = x search rows (K=768).   bias = g_tb[batch][gn]
// B is (N,K-slice) row-major with leading dim ldb.
// ---------------------------------------------------------------------------
template<int AMODE>
__global__ void __launch_bounds__(256)
tc_gemm3x_gelu(const float* __restrict__ A, const float* __restrict__ x,
               const float* __restrict__ B, int ldb,
               const float* __restrict__ bias,
               float* __restrict__ C, int M, int N, int K)
{
    constexpr int BM = 128, BN = 128, BK = 16;
    constexpr int MT = 2, NT = 8;

    __shared__ float Ah[BK][BM+1], Al[BK][BM+1];
    __shared__ float Bh[BK][BN+1], Bl[BK][BN+1];

    const int m0 = blockIdx.y * BM;
    const int n0 = blockIdx.x * BN;
    const int tid  = threadIdx.x;
    const int lane = tid & 31;
    const int w    = tid >> 5;
    const int wm = w >> 1, wn = w & 1;
    const int g  = lane >> 2, tg = lane & 3;
    const int m0w = wm * 32, n0w = wn * 64;

    const int lrow = tid >> 2;
    const int lkc  = (tid & 3) * 4;

    float acc[MT][NT][4];
    #pragma unroll
    for (int i = 0; i < MT; i++)
        #pragma unroll
        for (int j = 0; j < NT; j++)
            #pragma unroll
            for (int r = 0; r < 4; r++) acc[i][j][r] = 0.f;

    float4 rA[2], rB[2];

    auto load_tiles = [&](int k0) {
        #pragma unroll
        for (int it = 0; it < 2; it++) {
            int row = lrow + it * 64;
            int gm  = m0 + row, gk = k0 + lkc;
            if (AMODE == 1) {
                int bx = gm >> 8, sx = gm & 255;
                rA[it] = *(const float4*)(x + ((size_t)bx*NV + 129 + sx)*DIM + gk);
            } else {
                rA[it] = *(const float4*)(A + (size_t)gm * K + gk);
            }
            int gn = n0 + row;
            rB[it] = (gn < N) ? *(const float4*)(B + (size_t)gn * ldb + gk)
                              : make_float4(0.f, 0.f, 0.f, 0.f);
        }
    };
    auto store_tiles = [&]() {
        #pragma unroll
        for (int it = 0; it < 2; it++) {
            int row = lrow + it * 64;
            float hx = to_tf32(rA[it].x), hy = to_tf32(rA[it].y),
                  hz = to_tf32(rA[it].z), hw = to_tf32(rA[it].w);
            Ah[lkc+0][row] = hx; Al[lkc+0][row] = to_tf32(rA[it].x - hx);
            Ah[lkc+1][row] = hy; Al[lkc+1][row] = to_tf32(rA[it].y - hy);
            Ah[lkc+2][row] = hz; Al[lkc+2][row] = to_tf32(rA[it].z - hz);
            Ah[lkc+3][row] = hw; Al[lkc+3][row] = to_tf32(rA[it].w - hw);
            hx = to_tf32(rB[it].x); hy = to_tf32(rB[it].y);
            hz = to_tf32(rB[it].z); hw = to_tf32(rB[it].w);
            Bh[lkc+0][row] = hx; Bl[lkc+0][row] = to_tf32(rB[it].x - hx);
            Bh[lkc+1][row] = hy; Bl[lkc+1][row] = to_tf32(rB[it].y - hy);
            Bh[lkc+2][row] = hz; Bl[lkc+2][row] = to_tf32(rB[it].z - hz);
            Bh[lkc+3][row] = hw; Bl[lkc+3][row] = to_tf32(rB[it].w - hw);
        }
    };

    load_tiles(0);
    for (int k0 = 0; k0 < K; k0 += BK) {
        store_tiles();
        __syncthreads();
        if (k0 + BK < K) load_tiles(k0 + BK);

        #pragma unroll
        for (int kk = 0; kk < BK; kk += 8) {
            uint32_t ah[MT][4], al[MT][4];
            #pragma unroll
            for (int i = 0; i < MT; i++) {
                ah[i][0] = __float_as_uint(Ah[kk+tg  ][m0w + i*16 + g    ]);
                ah[i][1] = __float_as_uint(Ah[kk+tg  ][m0w + i*16 + g + 8]);
                ah[i][2] = __float_as_uint(Ah[kk+tg+4][m0w + i*16 + g    ]);
                ah[i][3] = __float_as_uint(Ah[kk+tg+4][m0w + i*16 + g + 8]);
                al[i][0] = __float_as_uint(Al[kk+tg  ][m0w + i*16 + g    ]);
                al[i][1] = __float_as_uint(Al[kk+tg  ][m0w + i*16 + g + 8]);
                al[i][2] = __float_as_uint(Al[kk+tg+4][m0w + i*16 + g    ]);
                al[i][3] = __float_as_uint(Al[kk+tg+4][m0w + i*16 + g + 8]);
            }
            #pragma unroll
            for (int j = 0; j < NT; j++) {
                uint32_t bh2[2] = {
                    __float_as_uint(Bh[kk+tg  ][n0w + j*8 + g]),
                    __float_as_uint(Bh[kk+tg+4][n0w + j*8 + g])};
                uint32_t bl2[2] = {
                    __float_as_uint(Bl[kk+tg  ][n0w + j*8 + g]),
                    __float_as_uint(Bl[kk+tg+4][n0w + j*8 + g])};
                #pragma unroll
                for (int i = 0; i < MT; i++) {
                    mma_tf32(acc[i][j], ah[i], bl2);
                    mma_tf32(acc[i][j], al[i], bh2);
                    mma_tf32(acc[i][j], ah[i], bh2);
                }
            }
        }
        __syncthreads();
    }

    #pragma unroll
    for (int i = 0; i < MT; i++) {
        #pragma unroll
        for (int j = 0; j < NT; j++) {
            #pragma unroll
            for (int r = 0; r < 4; r++) {
                int gm = m0 + m0w + i*16 + g + ((r & 2) ? 8 : 0);
                int gn = n0 + n0w + j*8 + tg*2 + (r & 1);
                if (gm >= M || gn >= N) continue;
                float bv = (AMODE == 1) ? g_tb[(gm >> 8) * 384 + gn] : bias[gn];
                C[(size_t)gm * N + gn] = gelu_exact(acc[i][j][r] + bv);
            }
        }
    }
}

// ---------------------------------------------------------------------------
// tb[b][n] = tgt_rep[b] . W1b[n] + b1[n]   (W1b = dp1_w[:, 768:1536])
// ---------------------------------------------------------------------------
__global__ void tb_kernel(const float* __restrict__ dp1_w,
                          const float* __restrict__ dp1_b) {
    int b = blockIdx.x;
    int n = threadIdx.x;           // 384
    const float* tg = g_tgt + (size_t)b * DIM;
    const float* wr = dp1_w + (size_t)n * 1536 + DIM;
    float s = dp1_b[n];
    #pragma unroll 8
    for (int k = 0; k < DIM; k++)
        s = fmaf(tg[k], wr[k], s);
    g_tb[b * 384 + n] = s;
}

// ---------------------------------------------------------------------------
// Flash attention: QK^T -> online masked softmax -> PV, fused per 128-q tile.
// ---------------------------------------------------------------------------
namespace {
constexpr int BQ = 128, BKV = 64;
}

struct FlashSmem {
    float Qs[HD][BQ + 4];
    float Ks[HD][BKV + 4];
    float Vs[BKV][HD + 4];
    float Ps[BKV][BQ + 4];
    int   km[BKV];
};

__global__ void __launch_bounds__(256)
flash_kernel() {
    extern __shared__ char raw_smem[];
    FlashSmem& S = *reinterpret_cast<FlashSmem*>(raw_smem);

    const int bh = blockIdx.y;
    const int b  = bh / NH, h = bh % NH;
    const int q0 = blockIdx.x * BQ;
    const int tid  = threadIdx.x;
    const int lane = tid & 31;
    const int w    = tid >> 5;
    const int g  = lane >> 2, tg = lane & 3;
    const int mw = w * 16;
    const int* db = g_db + (size_t)b * SS;

    for (int idx = tid; idx < BQ * HD; idx += 256) {
        int q = idx >> 6, d = idx & 63;
        int gq = q0 + q;
        float v = (gq < NQ) ? g_q[((size_t)bh*NQ + gq)*HD + d] * ATT_SCALE : 0.f;
        S.Qs[d][q] = to_tf32(v);
    }

    const int r0 = q0 + mw + g, r1 = r0 + 8;
    const bool qT0 = (r0 >= 1 && r0 <= 64);
    const bool qT1 = (r1 >= 1 && r1 <= 64);
    const bool qP0 = (r0 >= 65 && r0 < NQ) ? (db[r0 - 65] != 0) : false;
    const bool qP1 = (r1 >= 65 && r1 < NQ) ? (db[r1 - 65] != 0) : false;

    float m0 = -INFINITY, m1 = -INFINITY, l0 = 0.f, l1 = 0.f;
    float accO[8][4];
    #pragma unroll
    for (int j = 0; j < 8; j++)
        #pragma unroll
        for (int r = 0; r < 4; r++) accO[j][r] = 0.f;

    for (int kt = 0; kt < 7; kt++) {
        __syncthreads();
        const int kbase = kt * BKV;
        for (int idx = tid; idx < BKV * HD; idx += 256) {
            int kv = idx >> 6, d = idx & 63;
            int k = kbase + kv;
            float kvl = 0.f, vvl = 0.f;
            if (k < NV) {
                kvl = g_k[((size_t)bh*NV + k)*HD + d];
                vvl = g_v[((size_t)bh*NV + k)*HD + d];
            }
            S.Ks[d][kv] = to_tf32(kvl);
            S.Vs[kv][d] = to_tf32(vvl);
        }
        if (tid < BKV) {
            int k = kbase + tid;
            int fl = 0;
            if (k < NV) {
                fl = 4;
                if (k >= 1 && k <= 128) fl |= 1;
                if (k >= 129 && db[k - 129] != 0) fl |= 2;
            }
            S.km[tid] = fl;
        }
        __syncthreads();

        float sacc[8][4];
        #pragma unroll
        for (int j = 0; j < 8; j++)
            #pragma unroll
            for (int r = 0; r < 4; r++) sacc[j][r] = 0.f;

        #pragma unroll
        for (int kk = 0; kk < HD; kk += 8) {
            uint32_t a[4];
            a[0] = __float_as_uint(S.Qs[kk+tg  ][mw + g    ]);
            a[1] = __float_as_uint(S.Qs[kk+tg  ][mw + g + 8]);
            a[2] = __float_as_uint(S.Qs[kk+tg+4][mw + g    ]);
            a[3] = __float_as_uint(S.Qs[kk+tg+4][mw + g + 8]);
            #pragma unroll
            for (int j = 0; j < 8; j++) {
                uint32_t b2[2] = {
                    __float_as_uint(S.Ks[kk+tg  ][j*8 + g]),
                    __float_as_uint(S.Ks[kk+tg+4][j*8 + g])};
                mma_tf32(sacc[j], a, b2);
            }
        }

        int fA[8], fB[8];
        float tm0 = -INFINITY, tm1 = -INFINITY;
        #pragma unroll
        for (int j = 0; j < 8; j++) {
            int kvA = j*8 + 2*tg;
            fA[j] = S.km[kvA];
            fB[j] = S.km[kvA + 1];
            if (fA[j] & 4) { tm0 = fmaxf(tm0, sacc[j][0]); tm1 = fmaxf(tm1, sacc[j][2]); }
            if (fB[j] & 4) { tm0 = fmaxf(tm0, sacc[j][1]); tm1 = fmaxf(tm1, sacc[j][3]); }
        }
        #pragma unroll
        for (int o = 1; o <= 2; o <<= 1) {
            tm0 = fmaxf(tm0, __shfl_xor_sync(0xffffffffu, tm0, o));
            tm1 = fmaxf(tm1, __shfl_xor_sync(0xffffffffu, tm1, o));
        }
        float nm0 = fmaxf(m0, tm0), nm1 = fmaxf(m1, tm1);
        float f0 = __expf(m0 - nm0), f1 = __expf(m1 - nm1);

        float rs0 = 0.f, rs1 = 0.f;
        #pragma unroll
        for (int j = 0; j < 8; j++) {
            bool mA0 = (fA[j] & 4) && !((qT0 && (fA[j] & 2)) || (qP0 && (fA[j] & 1)));
            bool mB0 = (fB[j] & 4) && !((qT0 && (fB[j] & 2)) || (qP0 && (fB[j] & 1)));
            bool mA1 = (fA[j] & 4) && !((qT1 && (fA[j] & 2)) || (qP1 && (fA[j] & 1)));
            bool mB1 = (fB[j] & 4) && !((qT1 && (fB[j] & 2)) || (qP1 && (fB[j] & 1)));
            float e00 = mA0 ? __expf(sacc[j][0] - nm0) : 0.f;
            float e01 = mB0 ? __expf(sacc[j][1] - nm0) : 0.f;
            float e10 = mA1 ? __expf(sacc[j][2] - nm1) : 0.f;
            float e11 = mB1 ? __expf(sacc[j][3] - nm1) : 0.f;
            rs0 += e00 + e01;
            rs1 += e10 + e11;
            int kvA = j*8 + 2*tg;
            S.Ps[kvA    ][mw + g    ] = to_tf32(e00);
            S.Ps[kvA + 1][mw + g    ] = to_tf32(e01);
            S.Ps[kvA    ][mw + g + 8] = to_tf32(e10);
            S.Ps[kvA + 1][mw + g + 8] = to_tf32(e11);
        }
        #pragma unroll
        for (int o = 1; o <= 2; o <<= 1) {
            rs0 += __shfl_xor_sync(0xffffffffu, rs0, o);
            rs1 += __shfl_xor_sync(0xffffffffu, rs1, o);
        }
        l0 = l0 * f0 + rs0;
        l1 = l1 * f1 + rs1;
        #pragma unroll
        for (int j = 0; j < 8; j++) {
            accO[j][0] *= f0; accO[j][1] *= f0;
            accO[j][2] *= f1; accO[j][3] *= f1;
        }
        m0 = nm0; m1 = nm1;
        __syncwarp();

        #pragma unroll
        for (int kk = 0; kk < BKV; kk += 8) {
            uint32_t a[4];
            a[0] = __float_as_uint(S.Ps[kk+tg  ][mw + g    ]);
            a[1] = __float_as_uint(S.Ps[kk+tg  ][mw + g + 8]);
            a[2] = __float_as_uint(S.Ps[kk+tg+4][mw + g    ]);
            a[3] = __float_as_uint(S.Ps[kk+tg+4][mw + g + 8]);
            #pragma unroll
            for (int j = 0; j < 8; j++) {
                uint32_t b2[2] = {
                    __float_as_uint(S.Vs[kk+tg  ][j*8 + g]),
                    __float_as_uint(S.Vs[kk+tg+4][j*8 + g])};
                mma_tf32(accO[j], a, b2);
            }
        }
    }

    const float inv0 = 1.f / (l0 + EPS);
    const float inv1 = 1.f / (l1 + EPS);
    const float c = EPS / (float)NQ;
    #pragma unroll
    for (int j = 0; j < 8; j++) {
        #pragma unroll
        for (int r = 0; r < 4; r++) {
            int d = j*8 + 2*tg + (r & 1);
            int q = q0 + mw + g + ((r & 2) ? 8 : 0);
            if (q >= NQ) continue;
            float vs = g_vsum[bh * HD + d];
            float val = (accO[j][r] + c * vs) * ((r & 2) ? inv1 : inv0);
            g_ao[((size_t)b*NQ + q)*DIM + h*HD + d] = val;
        }
    }
}

// ---------------------------------------------------------------------------
// small kernels
// ---------------------------------------------------------------------------
__global__ void mean_kernel(const float* __restrict__ x) {
    int b = blockIdx.x;
    int c = threadIdx.x;
    float s = 0.f;
    #pragma unroll 8
    for (int t = 0; t < 64; t++)
        s += x[((size_t)b*NV + 65 + t)*DIM + c];
    g_tgt[b*DIM + c] = s * (1.0f/64.0f);
}

__global__ void mlp3_kernel(const float* __restrict__ w3,
                            const float* __restrict__ b3) {
    int gwarp = (blockIdx.x * blockDim.x + threadIdx.x) >> 5;
    int lane  = threadIdx.x & 31;
    if (gwarp >= TOKENS) return;
    const float* row = g_h2 + (size_t)gwarp * 192;
    float s0 = 0.f, s1 = 0.f;
    for (int k = lane; k < 192; k += 32) {
        float xv = row[k];
        s0 = fmaf(xv, w3[k],       s0);
        s1 = fmaf(xv, w3[192 + k], s1);
    }
    #pragma unroll
    for (int o = 16; o; o >>= 1) {
        s0 += __shfl_xor_sync(0xffffffffu, s0, o);
        s1 += __shfl_xor_sync(0xffffffffu, s1, o);
    }
    if (lane == 0)
        g_db[gwarp] = (s0 + b3[0] >= s1 + b3[1]) ? 1 : 0;
}

__global__ void vsum_kernel() {
    int bh = blockIdx.x;
    int d  = threadIdx.x;
    float s = 0.f;
    for (int k = 0; k < NV; k++)
        s += g_v[((size_t)bh*NV + k)*HD + d];
    g_vsum[bh*HD + d] = s;
}

// ---------------------------------------------------------------------------
extern "C" void kernel_launch(void* const* d_in, const int* in_sizes, int n_in,
                              void* d_out, int out_size) {
    const float* x      = (const float*)d_in[0];
    const float* qkv_w  = (const float*)d_in[2];
    const float* qkv_b  = (const float*)d_in[3];
    const float* proj_w = (const float*)d_in[4];
    const float* proj_b = (const float*)d_in[5];
    const float* dp1_w  = (const float*)d_in[6];
    const float* dp1_b  = (const float*)d_in[7];
    const float* dp2_w  = (const float*)d_in[8];
    const float* dp2_b  = (const float*)d_in[9];
    const float* dp3_w  = (const float*)d_in[10];
    const float* dp3_b  = (const float*)d_in[11];
    float* out = (float*)d_out;

    float *p_h1, *p_h2, *p_ao;
    cudaGetSymbolAddress((void**)&p_h1, g_h1);
    cudaGetSymbolAddress((void**)&p_h2, g_h2);
    cudaGetSymbolAddress((void**)&p_ao, g_ao);

    auto cdiv = [](int a, int b) { return (a + b - 1) / b; };

    // decision path
    mean_kernel<<<B_, DIM>>>(x);
    tb_kernel<<<B_, 384>>>(dp1_w, dp1_b);
    tc_gemm3x_gelu<1><<<dim3(3, 128), 256>>>(
        nullptr, x, dp1_w, 1536, nullptr, p_h1, TOKENS, 384, DIM);
    tc_gemm3x_gelu<0><<<dim3(2, 128), 256>>>(
        p_h1, nullptr, dp2_w, 384, dp2_b, p_h2, TOKENS, 192, 384);
    mlp3_kernel<<<cdiv(TOKENS*32, 256), 256>>>(dp3_w, dp3_b);

    // QKV projection + head scatter
    tc_gemm<2><<<dim3(cdiv(QKVD,128), cdiv(B_*NV,128)), 256>>>(
        x, qkv_w, qkv_b, nullptr, B_*NV, QKVD, DIM);

    // V column sums (for eps/NQ term)
    vsum_kernel<<<BH, HD>>>();

    // fused attention
    constexpr size_t FLASH_SMEM = sizeof(FlashSmem);
    cudaFuncSetAttribute(flash_kernel,
                         cudaFuncAttributeMaxDynamicSharedMemorySize,
                         (int)FLASH_SMEM);
    flash_kernel<<<dim3(cdiv(NQ, BQ), BH), 256, FLASH_SMEM>>>();

    // output projection
    tc_gemm<0><<<dim3(cdiv(DIM,128), cdiv(B_*NQ,128)), 256>>>(
        p_ao, proj_w, proj_b, out, B_*NQ, DIM, DIM);
}

// round 5
// speedup vs baseline: 2.4036x; 1.3127x over previous
#include <cuda_runtime.h>
#include <math.h>
#include <stdint.h>

namespace {
constexpr int B_   = 64;
constexpr int NV   = 385;
constexpr int NQ   = 321;
constexpr int SS   = 256;
constexpr int NH   = 12;
constexpr int HD   = 64;
constexpr int DIM  = 768;
constexpr int QKVD = 2304;
constexpr int BH   = B_ * NH;
constexpr int TOKENS = B_ * SS;
constexpr float ATT_SCALE = 0.125f;
constexpr float EPS = 1e-6f;
}

__device__ float g_tgt[B_ * DIM];
__device__ float g_tb[B_ * 384];
__device__ float g_h1[(size_t)TOKENS * 384];
__device__ float g_h2[(size_t)TOKENS * 192];
__device__ int   g_db[TOKENS];
__device__ float g_q [(size_t)BH * NQ * HD];
__device__ float g_k [(size_t)BH * NV * HD];
__device__ float g_v [(size_t)BH * NV * HD];
__device__ float g_vsum[BH * HD];
__device__ float g_ao[(size_t)B_ * NQ * DIM];

__device__ __forceinline__ float gelu_exact(float x) {
    return 0.5f * x * (1.0f + erff(x * 0.70710678118654752440f));
}

__device__ __forceinline__ float to_tf32(float x) {
    uint32_t r;
    asm("cvt.rna.tf32.f32 %0, %1;" : "=r"(r) : "f"(x));
    return __uint_as_float(r);
}

__device__ __forceinline__ void mma_tf32(float c[4], const uint32_t a[4],
                                         const uint32_t b[2]) {
    asm volatile(
        "mma.sync.aligned.m16n8k8.row.col.f32.tf32.tf32.f32 "
        "{%0,%1,%2,%3}, {%4,%5,%6,%7}, {%8,%9}, {%0,%1,%2,%3};"
        : "+f"(c[0]), "+f"(c[1]), "+f"(c[2]), "+f"(c[3])
        : "r"(a[0]), "r"(a[1]), "r"(a[2]), "r"(a[3]),
          "r"(b[0]), "r"(b[1]));
}

// Swizzled smem tile layout: T[row][16], element (row,k) stored at column
//   4*((k&3) ^ ((row>>1)&3)) + (k>>2)
// Fragment thread (g = lane>>2, tg = lane&3) reads its full 16-k slice of a
// row (k = tg, tg+4, tg+8, tg+12 -> x,y,z,w) as ONE float4 at column
//   4*(tg ^ (g>>1)).
// Both stores and loads are bank-conflict-free.

// ---------------------------------------------------------------------------
// TF32 tensor-core GEMM. B is (N,K) row-major, K multiple of 16.
// MODE: 0 bias+store, 2 qkv scatter
// ---------------------------------------------------------------------------
template<int MODE>
__global__ void __launch_bounds__(256, 2)
tc_gemm(const float* __restrict__ A, const float* __restrict__ B,
        const float* __restrict__ bias, float* __restrict__ C,
        int M, int N, int K)
{
    constexpr int BM = 128, BN = 128, BK = 16;

    __shared__ float As[BM][BK];
    __shared__ float Bs[BN][BK];

    const int m0 = blockIdx.y * BM;
    const int n0 = blockIdx.x * BN;
    const int tid  = threadIdx.x;
    const int lane = tid & 31;
    const int w    = tid >> 5;
    const int wm = w >> 1, wn = w & 1;
    const int g  = lane >> 2, tg = lane & 3;
    const int m0w = wm * 32, n0w = wn * 64;

    const int lrow = tid >> 2;        // 0..63 (+64)
    const int lc   = tid & 3;         // e = k>>2
    const int lkc  = lc * 4;          // gmem k offset
    const int colL = 4 * (tg ^ (g >> 1));

    float acc[2][8][4];
    #pragma unroll
    for (int i = 0; i < 2; i++)
        #pragma unroll
        for (int j = 0; j < 8; j++)
            #pragma unroll
            for (int r = 0; r < 4; r++) acc[i][j][r] = 0.f;

    for (int k0 = 0; k0 < K; k0 += BK) {
        #pragma unroll
        for (int it = 0; it < 2; it++) {
            int row = lrow + it * 64;
            int p4  = ((row >> 1) & 3);
            int gm  = m0 + row;
            float4 v = (gm < M) ? *(const float4*)(A + (size_t)gm * K + k0 + lkc)
                                : make_float4(0.f, 0.f, 0.f, 0.f);
            As[row][4*(0^p4) + lc] = to_tf32(v.x);
            As[row][4*(1^p4) + lc] = to_tf32(v.y);
            As[row][4*(2^p4) + lc] = to_tf32(v.z);
            As[row][4*(3^p4) + lc] = to_tf32(v.w);
            int gn = n0 + row;
            float4 u = (gn < N) ? *(const float4*)(B + (size_t)gn * K + k0 + lkc)
                                : make_float4(0.f, 0.f, 0.f, 0.f);
            Bs[row][4*(0^p4) + lc] = to_tf32(u.x);
            Bs[row][4*(1^p4) + lc] = to_tf32(u.y);
            Bs[row][4*(2^p4) + lc] = to_tf32(u.z);
            Bs[row][4*(3^p4) + lc] = to_tf32(u.w);
        }
        __syncthreads();

        float4 va[4];
        va[0] = *(const float4*)&As[m0w + g     ][colL];
        va[1] = *(const float4*)&As[m0w + g +  8][colL];
        va[2] = *(const float4*)&As[m0w + g + 16][colL];
        va[3] = *(const float4*)&As[m0w + g + 24][colL];
        float4 vb[8];
        #pragma unroll
        for (int j = 0; j < 8; j++)
            vb[j] = *(const float4*)&Bs[n0w + j*8 + g][colL];

        #pragma unroll
        for (int i = 0; i < 2; i++) {
            uint32_t a0[4] = {
                __float_as_uint(va[2*i].x), __float_as_uint(va[2*i+1].x),
                __float_as_uint(va[2*i].y), __float_as_uint(va[2*i+1].y)};
            uint32_t a8[4] = {
                __float_as_uint(va[2*i].z), __float_as_uint(va[2*i+1].z),
                __float_as_uint(va[2*i].w), __float_as_uint(va[2*i+1].w)};
            #pragma unroll
            for (int j = 0; j < 8; j++) {
                uint32_t b0[2] = {__float_as_uint(vb[j].x), __float_as_uint(vb[j].y)};
                uint32_t b8[2] = {__float_as_uint(vb[j].z), __float_as_uint(vb[j].w)};
                mma_tf32(acc[i][j], a0, b0);
                mma_tf32(acc[i][j], a8, b8);
            }
        }
        __syncthreads();
    }

    #pragma unroll
    for (int i = 0; i < 2; i++) {
        #pragma unroll
        for (int j = 0; j < 8; j++) {
            #pragma unroll
            for (int r = 0; r < 4; r++) {
                int gm = m0 + m0w + i*16 + g + ((r & 2) ? 8 : 0);
                int gn = n0 + n0w + j*8 + tg*2 + (r & 1);
                if (gm >= M || gn >= N) continue;
                float v = acc[i][j][r];
                if (MODE == 0) {
                    C[(size_t)gm * N + gn] = v + bias[gn];
                } else {
                    float t = v + bias[gn];
                    int bb = gm / NV, nv = gm % NV;
                    int typ = gn / DIM;
                    int hd  = gn % DIM;
                    int h = hd >> 6, d = hd & 63;
                    if (typ == 1) {
                        g_k[(((size_t)bb*NH + h)*NV + nv)*HD + d] = t;
                    } else if (typ == 2) {
                        g_v[(((size_t)bb*NH + h)*NV + nv)*HD + d] = t;
                    } else {
                        int qi = (nv == 0) ? 0 : (nv >= 65 ? nv - 64 : -1);
                        if (qi >= 0)
                            g_q[(((size_t)bb*NH + h)*NQ + qi)*HD + d] = t;
                    }
                }
            }
        }
    }
}

// ---------------------------------------------------------------------------
// 3xTF32 GEMM + GELU (fp32-accurate hi/lo split), swizzled wide-load scheme.
// AMODE 0: A = given pointer (M,K), bias[gn].
// AMODE 1: A = x search rows (K=768), bias = g_tb[batch][gn].
// B is (N,K-slice) row-major with leading dim ldb.
// ---------------------------------------------------------------------------
template<int AMODE>
__global__ void __launch_bounds__(256, 2)
tc_gemm3x_gelu(const float* __restrict__ A, const float* __restrict__ x,
               const float* __restrict__ B, int ldb,
               const float* __restrict__ bias,
               float* __restrict__ C, int M, int N, int K)
{
    constexpr int BM = 128, BN = 128, BK = 16;

    __shared__ float Ah[BM][BK], Al[BM][BK];
    __shared__ float Bh[BN][BK], Bl[BN][BK];

    const int m0 = blockIdx.y * BM;
    const int n0 = blockIdx.x * BN;
    const int tid  = threadIdx.x;
    const int lane = tid & 31;
    const int w    = tid >> 5;
    const int wm = w >> 1, wn = w & 1;
    const int g  = lane >> 2, tg = lane & 3;
    const int m0w = wm * 32, n0w = wn * 64;

    const int lrow = tid >> 2;
    const int lc   = tid & 3;
    const int lkc  = lc * 4;
    const int colL = 4 * (tg ^ (g >> 1));

    float acc[2][8][4];
    #pragma unroll
    for (int i = 0; i < 2; i++)
        #pragma unroll
        for (int j = 0; j < 8; j++)
            #pragma unroll
            for (int r = 0; r < 4; r++) acc[i][j][r] = 0.f;

    for (int k0 = 0; k0 < K; k0 += BK) {
        #pragma unroll
        for (int it = 0; it < 2; it++) {
            int row = lrow + it * 64;
            int p4  = ((row >> 1) & 3);
            int gm  = m0 + row;
            float4 v;
            if (AMODE == 1) {
                int bx = gm >> 8, sx = gm & 255;
                v = *(const float4*)(x + ((size_t)bx*NV + 129 + sx)*DIM + k0 + lkc);
            } else {
                v = *(const float4*)(A + (size_t)gm * K + k0 + lkc);
            }
            float hx = to_tf32(v.x), hy = to_tf32(v.y),
                  hz = to_tf32(v.z), hw = to_tf32(v.w);
            Ah[row][4*(0^p4)+lc] = hx; Al[row][4*(0^p4)+lc] = to_tf32(v.x - hx);
            Ah[row][4*(1^p4)+lc] = hy; Al[row][4*(1^p4)+lc] = to_tf32(v.y - hy);
            Ah[row][4*(2^p4)+lc] = hz; Al[row][4*(2^p4)+lc] = to_tf32(v.z - hz);
            Ah[row][4*(3^p4)+lc] = hw; Al[row][4*(3^p4)+lc] = to_tf32(v.w - hw);
            int gn = n0 + row;
            float4 u = (gn < N) ? *(const float4*)(B + (size_t)gn * ldb + k0 + lkc)
                                : make_float4(0.f, 0.f, 0.f, 0.f);
            hx = to_tf32(u.x); hy = to_tf32(u.y);
            hz = to_tf32(u.z); hw = to_tf32(u.w);
            Bh[row][4*(0^p4)+lc] = hx; Bl[row][4*(0^p4)+lc] = to_tf32(u.x - hx);
            Bh[row][4*(1^p4)+lc] = hy; Bl[row][4*(1^p4)+lc] = to_tf32(u.y - hy);
            Bh[row][4*(2^p4)+lc] = hz; Bl[row][4*(2^p4)+lc] = to_tf32(u.z - hz);
            Bh[row][4*(3^p4)+lc] = hw; Bl[row][4*(3^p4)+lc] = to_tf32(u.w - hw);
        }
        __syncthreads();

        float4 vah[4], val_[4];
        #pragma unroll
        for (int i = 0; i < 4; i++) {
            int row = m0w + g + i*8;
            vah[i]  = *(const float4*)&Ah[row][colL];
            val_[i] = *(const float4*)&Al[row][colL];
        }

        #pragma unroll
        for (int j = 0; j < 8; j++) {
            float4 vbh = *(const float4*)&Bh[n0w + j*8 + g][colL];
            float4 vbl = *(const float4*)&Bl[n0w + j*8 + g][colL];
            uint32_t bh0[2] = {__float_as_uint(vbh.x), __float_as_uint(vbh.y)};
            uint32_t bh8[2] = {__float_as_uint(vbh.z), __float_as_uint(vbh.w)};
            uint32_t bl0[2] = {__float_as_uint(vbl.x), __float_as_uint(vbl.y)};
            uint32_t bl8[2] = {__float_as_uint(vbl.z), __float_as_uint(vbl.w)};
            #pragma unroll
            for (int i = 0; i < 2; i++) {
                uint32_t ah0[4] = {
                    __float_as_uint(vah[2*i].x), __float_as_uint(vah[2*i+1].x),
                    __float_as_uint(vah[2*i].y), __float_as_uint(vah[2*i+1].y)};
                uint32_t ah8[4] = {
                    __float_as_uint(vah[2*i].z), __float_as_uint(vah[2*i+1].z),
                    __float_as_uint(vah[2*i].w), __float_as_uint(vah[2*i+1].w)};
                uint32_t al0[4] = {
                    __float_as_uint(val_[2*i].x), __float_as_uint(val_[2*i+1].x),
                    __float_as_uint(val_[2*i].y), __float_as_uint(val_[2*i+1].y)};
                uint32_t al8[4] = {
                    __float_as_uint(val_[2*i].z), __float_as_uint(val_[2*i+1].z),
                    __float_as_uint(val_[2*i].w), __float_as_uint(val_[2*i+1].w)};
                mma_tf32(acc[i][j], ah0, bl0);
                mma_tf32(acc[i][j], al0, bh0);
                mma_tf32(acc[i][j], ah0, bh0);
                mma_tf32(acc[i][j], ah8, bl8);
                mma_tf32(acc[i][j], al8, bh8);
                mma_tf32(acc[i][j], ah8, bh8);
            }
        }
        __syncthreads();
    }

    #pragma unroll
    for (int i = 0; i < 2; i++) {
        #pragma unroll
        for (int j = 0; j < 8; j++) {
            #pragma unroll
            for (int r = 0; r < 4; r++) {
                int gm = m0 + m0w + i*16 + g + ((r & 2) ? 8 : 0);
                int gn = n0 + n0w + j*8 + tg*2 + (r & 1);
                if (gm >= M || gn >= N) continue;
                float bv = (AMODE == 1) ? g_tb[(gm >> 8) * 384 + gn] : bias[gn];
                C[(size_t)gm * N + gn] = gelu_exact(acc[i][j][r] + bv);
            }
        }
    }
}

// ---------------------------------------------------------------------------
// tb[b][n] = tgt_rep[b] . W1b[n] + b1[n]   (W1b = dp1_w[:, 768:1536])
// ---------------------------------------------------------------------------
__global__ void tb_kernel(const float* __restrict__ dp1_w,
                          const float* __restrict__ dp1_b) {
    int b = blockIdx.x;
    int n = threadIdx.x;           // 384
    const float* tg = g_tgt + (size_t)b * DIM;
    const float* wr = dp1_w + (size_t)n * 1536 + DIM;
    float s = dp1_b[n];
    #pragma unroll 8
    for (int k = 0; k < DIM; k++)
        s = fmaf(tg[k], wr[k], s);
    g_tb[b * 384 + n] = s;
}

// ---------------------------------------------------------------------------
// Flash attention (unchanged from R4)
// ---------------------------------------------------------------------------
namespace {
constexpr int BQ = 128, BKV = 64;
}

struct FlashSmem {
    float Qs[HD][BQ + 4];
    float Ks[HD][BKV + 4];
    float Vs[BKV][HD + 4];
    float Ps[BKV][BQ + 4];
    int   km[BKV];
};

__global__ void __launch_bounds__(256)
flash_kernel() {
    extern __shared__ char raw_smem[];
    FlashSmem& S = *reinterpret_cast<FlashSmem*>(raw_smem);

    const int bh = blockIdx.y;
    const int b  = bh / NH, h = bh % NH;
    const int q0 = blockIdx.x * BQ;
    const int tid  = threadIdx.x;
    const int lane = tid & 31;
    const int w    = tid >> 5;
    const int g  = lane >> 2, tg = lane & 3;
    const int mw = w * 16;
    const int* db = g_db + (size_t)b * SS;

    for (int idx = tid; idx < BQ * HD; idx += 256) {
        int q = idx >> 6, d = idx & 63;
        int gq = q0 + q;
        float v = (gq < NQ) ? g_q[((size_t)bh*NQ + gq)*HD + d] * ATT_SCALE : 0.f;
        S.Qs[d][q] = to_tf32(v);
    }

    const int r0 = q0 + mw + g, r1 = r0 + 8;
    const bool qT0 = (r0 >= 1 && r0 <= 64);
    const bool qT1 = (r1 >= 1 && r1 <= 64);
    const bool qP0 = (r0 >= 65 && r0 < NQ) ? (db[r0 - 65] != 0) : false;
    const bool qP1 = (r1 >= 65 && r1 < NQ) ? (db[r1 - 65] != 0) : false;

    float m0 = -INFINITY, m1 = -INFINITY, l0 = 0.f, l1 = 0.f;
    float accO[8][4];
    #pragma unroll
    for (int j = 0; j < 8; j++)
        #pragma unroll
        for (int r = 0; r < 4; r++) accO[j][r] = 0.f;

    for (int kt = 0; kt < 7; kt++) {
        __syncthreads();
        const int kbase = kt * BKV;
        for (int idx = tid; idx < BKV * HD; idx += 256) {
            int kv = idx >> 6, d = idx & 63;
            int k = kbase + kv;
            float kvl = 0.f, vvl = 0.f;
            if (k < NV) {
                kvl = g_k[((size_t)bh*NV + k)*HD + d];
                vvl = g_v[((size_t)bh*NV + k)*HD + d];
            }
            S.Ks[d][kv] = to_tf32(kvl);
            S.Vs[kv][d] = to_tf32(vvl);
        }
        if (tid < BKV) {
            int k = kbase + tid;
            int fl = 0;
            if (k < NV) {
                fl = 4;
                if (k >= 1 && k <= 128) fl |= 1;
                if (k >= 129 && db[k - 129] != 0) fl |= 2;
            }
            S.km[tid] = fl;
        }
        __syncthreads();

        float sacc[8][4];
        #pragma unroll
        for (int j = 0; j < 8; j++)
            #pragma unroll
            for (int r = 0; r < 4; r++) sacc[j][r] = 0.f;

        #pragma unroll
        for (int kk = 0; kk < HD; kk += 8) {
            uint32_t a[4];
            a[0] = __float_as_uint(S.Qs[kk+tg  ][mw + g    ]);
            a[1] = __float_as_uint(S.Qs[kk+tg  ][mw + g + 8]);
            a[2] = __float_as_uint(S.Qs[kk+tg+4][mw + g    ]);
            a[3] = __float_as_uint(S.Qs[kk+tg+4][mw + g + 8]);
            #pragma unroll
            for (int j = 0; j < 8; j++) {
                uint32_t b2[2] = {
                    __float_as_uint(S.Ks[kk+tg  ][j*8 + g]),
                    __float_as_uint(S.Ks[kk+tg+4][j*8 + g])};
                mma_tf32(sacc[j], a, b2);
            }
        }

        int fA[8], fB[8];
        float tm0 = -INFINITY, tm1 = -INFINITY;
        #pragma unroll
        for (int j = 0; j < 8; j++) {
            int kvA = j*8 + 2*tg;
            fA[j] = S.km[kvA];
            fB[j] = S.km[kvA + 1];
            if (fA[j] & 4) { tm0 = fmaxf(tm0, sacc[j][0]); tm1 = fmaxf(tm1, sacc[j][2]); }
            if (fB[j] & 4) { tm0 = fmaxf(tm0, sacc[j][1]); tm1 = fmaxf(tm1, sacc[j][3]); }
        }
        #pragma unroll
        for (int o = 1; o <= 2; o <<= 1) {
            tm0 = fmaxf(tm0, __shfl_xor_sync(0xffffffffu, tm0, o));
            tm1 = fmaxf(tm1, __shfl_xor_sync(0xffffffffu, tm1, o));
        }
        float nm0 = fmaxf(m0, tm0), nm1 = fmaxf(m1, tm1);
        float f0 = __expf(m0 - nm0), f1 = __expf(m1 - nm1);

        float rs0 = 0.f, rs1 = 0.f;
        #pragma unroll
        for (int j = 0; j < 8; j++) {
            bool mA0 = (fA[j] & 4) && !((qT0 && (fA[j] & 2)) || (qP0 && (fA[j] & 1)));
            bool mB0 = (fB[j] & 4) && !((qT0 && (fB[j] & 2)) || (qP0 && (fB[j] & 1)));
            bool mA1 = (fA[j] & 4) && !((qT1 && (fA[j] & 2)) || (qP1 && (fA[j] & 1)));
            bool mB1 = (fB[j] & 4) && !((qT1 && (fB[j] & 2)) || (qP1 && (fB[j] & 1)));
            float e00 = mA0 ? __expf(sacc[j][0] - nm0) : 0.f;
            float e01 = mB0 ? __expf(sacc[j][1] - nm0) : 0.f;
            float e10 = mA1 ? __expf(sacc[j][2] - nm1) : 0.f;
            float e11 = mB1 ? __expf(sacc[j][3] - nm1) : 0.f;
            rs0 += e00 + e01;
            rs1 += e10 + e11;
            int kvA = j*8 + 2*tg;
            S.Ps[kvA    ][mw + g    ] = to_tf32(e00);
            S.Ps[kvA + 1][mw + g    ] = to_tf32(e01);
            S.Ps[kvA    ][mw + g + 8] = to_tf32(e10);
            S.Ps[kvA + 1][mw + g + 8] = to_tf32(e11);
        }
        #pragma unroll
        for (int o = 1; o <= 2; o <<= 1) {
            rs0 += __shfl_xor_sync(0xffffffffu, rs0, o);
            rs1 += __shfl_xor_sync(0xffffffffu, rs1, o);
        }
        l0 = l0 * f0 + rs0;
        l1 = l1 * f1 + rs1;
        #pragma unroll
        for (int j = 0; j < 8; j++) {
            accO[j][0] *= f0; accO[j][1] *= f0;
            accO[j][2] *= f1; accO[j][3] *= f1;
        }
        m0 = nm0; m1 = nm1;
        __syncwarp();

        #pragma unroll
        for (int kk = 0; kk < BKV; kk += 8) {
            uint32_t a[4];
            a[0] = __float_as_uint(S.Ps[kk+tg  ][mw + g    ]);
            a[1] = __float_as_uint(S.Ps[kk+tg  ][mw + g + 8]);
            a[2] = __float_as_uint(S.Ps[kk+tg+4][mw + g    ]);
            a[3] = __float_as_uint(S.Ps[kk+tg+4][mw + g + 8]);
            #pragma unroll
            for (int j = 0; j < 8; j++) {
                uint32_t b2[2] = {
                    __float_as_uint(S.Vs[kk+tg  ][j*8 + g]),
                    __float_as_uint(S.Vs[kk+tg+4][j*8 + g])};
                mma_tf32(accO[j], a, b2);
            }
        }
    }

    const float inv0 = 1.f / (l0 + EPS);
    const float inv1 = 1.f / (l1 + EPS);
    const float c = EPS / (float)NQ;
    #pragma unroll
    for (int j = 0; j < 8; j++) {
        #pragma unroll
        for (int r = 0; r < 4; r++) {
            int d = j*8 + 2*tg + (r & 1);
            int q = q0 + mw + g + ((r & 2) ? 8 : 0);
            if (q >= NQ) continue;
            float vs = g_vsum[bh * HD + d];
            float val = (accO[j][r] + c * vs) * ((r & 2) ? inv1 : inv0);
            g_ao[((size_t)b*NQ + q)*DIM + h*HD + d] = val;
        }
    }
}

// ---------------------------------------------------------------------------
// small kernels
// ---------------------------------------------------------------------------
__global__ void mean_kernel(const float* __restrict__ x) {
    int b = blockIdx.x;
    int c = threadIdx.x;
    float s = 0.f;
    #pragma unroll 8
    for (int t = 0; t < 64; t++)
        s += x[((size_t)b*NV + 65 + t)*DIM + c];
    g_tgt[b*DIM + c] = s * (1.0f/64.0f);
}

__global__ void mlp3_kernel(const float* __restrict__ w3,
                            const float* __restrict__ b3) {
    int gwarp = (blockIdx.x * blockDim.x + threadIdx.x) >> 5;
    int lane  = threadIdx.x & 31;
    if (gwarp >= TOKENS) return;
    const float* row = g_h2 + (size_t)gwarp * 192;
    float s0 = 0.f, s1 = 0.f;
    for (int k = lane; k < 192; k += 32) {
        float xv = row[k];
        s0 = fmaf(xv, w3[k],       s0);
        s1 = fmaf(xv, w3[192 + k], s1);
    }
    #pragma unroll
    for (int o = 16; o; o >>= 1) {
        s0 += __shfl_xor_sync(0xffffffffu, s0, o);
        s1 += __shfl_xor_sync(0xffffffffu, s1, o);
    }
    if (lane == 0)
        g_db[gwarp] = (s0 + b3[0] >= s1 + b3[1]) ? 1 : 0;
}

__global__ void vsum_kernel() {
    int bh = blockIdx.x;
    int d  = threadIdx.x;
    float s = 0.f;
    for (int k = 0; k < NV; k++)
        s += g_v[((size_t)bh*NV + k)*HD + d];
    g_vsum[bh*HD + d] = s;
}

// ---------------------------------------------------------------------------
extern "C" void kernel_launch(void* const* d_in, const int* in_sizes, int n_in,
                              void* d_out, int out_size) {
    const float* x      = (const float*)d_in[0];
    const float* qkv_w  = (const float*)d_in[2];
    const float* qkv_b  = (const float*)d_in[3];
    const float* proj_w = (const float*)d_in[4];
    const float* proj_b = (const float*)d_in[5];
    const float* dp1_w  = (const float*)d_in[6];
    const float* dp1_b  = (const float*)d_in[7];
    const float* dp2_w  = (const float*)d_in[8];
    const float* dp2_b  = (const float*)d_in[9];
    const float* dp3_w  = (const float*)d_in[10];
    const float* dp3_b  = (const float*)d_in[11];
    float* out = (float*)d_out;

    float *p_h1, *p_h2, *p_ao;
    cudaGetSymbolAddress((void**)&p_h1, g_h1);
    cudaGetSymbolAddress((void**)&p_h2, g_h2);
    cudaGetSymbolAddress((void**)&p_ao, g_ao);

    auto cdiv = [](int a, int b) { return (a + b - 1) / b; };

    // decision path
    mean_kernel<<<B_, DIM>>>(x);
    tb_kernel<<<B_, 384>>>(dp1_w, dp1_b);
    tc_gemm3x_gelu<1><<<dim3(3, 128), 256>>>(
        nullptr, x, dp1_w, 1536, nullptr, p_h1, TOKENS, 384, DIM);
    tc_gemm3x_gelu<0><<<dim3(2, 128), 256>>>(
        p_h1, nullptr, dp2_w, 384, dp2_b, p_h2, TOKENS, 192, 384);
    mlp3_kernel<<<cdiv(TOKENS*32, 256), 256>>>(dp3_w, dp3_b);

    // QKV projection + head scatter
    tc_gemm<2><<<dim3(cdiv(QKVD,128), cdiv(B_*NV,128)), 256>>>(
        x, qkv_w, qkv_b, nullptr, B_*NV, QKVD, DIM);

    // V column sums (for eps/NQ term)
    vsum_kernel<<<BH, HD>>>();

    // fused attention
    constexpr size_t FLASH_SMEM = sizeof(FlashSmem);
    cudaFuncSetAttribute(flash_kernel,
                         cudaFuncAttributeMaxDynamicSharedMemorySize,
                         (int)FLASH_SMEM);
    flash_kernel<<<dim3(cdiv(NQ, BQ), BH), 256, FLASH_SMEM>>>();

    // output projection
    tc_gemm<0><<<dim3(cdiv(DIM,128), cdiv(B_*NQ,128)), 256>>>(
        p_ao, proj_w, proj_b, out, B_*NQ, DIM, DIM);
}

// round 6
// speedup vs baseline: 2.5755x; 1.0715x over previous
#include <cuda_runtime.h>
#include <math.h>
#include <stdint.h>

namespace {
constexpr int B_   = 64;
constexpr int NV   = 385;
constexpr int NQ   = 321;
constexpr int SS   = 256;
constexpr int NH   = 12;
constexpr int HD   = 64;
constexpr int DIM  = 768;
constexpr int QKVD = 2304;
constexpr int BH   = B_ * NH;
constexpr int TOKENS = B_ * SS;
constexpr float ATT_SCALE = 0.125f;
constexpr float EPS = 1e-6f;
}

__device__ float g_tgt[B_ * DIM];
__device__ float g_tb[B_ * 384];
__device__ float g_h1[(size_t)TOKENS * 384];
__device__ float g_h2[(size_t)TOKENS * 192];
__device__ int   g_db[TOKENS];
__device__ float g_q [(size_t)BH * NQ * HD];
__device__ float g_k [(size_t)BH * NV * HD];
__device__ float g_v [(size_t)BH * NV * HD];
__device__ float g_vsum[BH * HD];
__device__ float g_ao[(size_t)B_ * NQ * DIM];

__device__ __forceinline__ float gelu_exact(float x) {
    return 0.5f * x * (1.0f + erff(x * 0.70710678118654752440f));
}

__device__ __forceinline__ float to_tf32(float x) {
    uint32_t r;
    asm("cvt.rna.tf32.f32 %0, %1;" : "=r"(r) : "f"(x));
    return __uint_as_float(r);
}

__device__ __forceinline__ void mma_tf32(float c[4], const uint32_t a[4],
                                         const uint32_t b[2]) {
    asm volatile(
        "mma.sync.aligned.m16n8k8.row.col.f32.tf32.tf32.f32 "
        "{%0,%1,%2,%3}, {%4,%5,%6,%7}, {%8,%9}, {%0,%1,%2,%3};"
        : "+f"(c[0]), "+f"(c[1]), "+f"(c[2]), "+f"(c[3])
        : "r"(a[0]), "r"(a[1]), "r"(a[2]), "r"(a[3]),
          "r"(b[0]), "r"(b[1]));
}

// Per-16k-subtile swizzled layout (proven conflict-free in R5):
// element (row,k) of a [128][16] tile stored at column
//   4*((k&3) ^ ((row>>1)&3)) + (k>>2)
// Fragment thread (g=lane>>2, tg=lane&3) reads its 16-k slice of a row as one
// float4 at column 4*(tg ^ (g>>1)) -> (.x,.y,.z,.w) = k (tg, tg+4, tg+8, tg+12)

// ---------------------------------------------------------------------------
// TF32 GEMM, two 16-k subtiles per barrier. B is (N,K) row-major, K % 32 == 0.
// MODE: 0 bias+store (requires N % 128 == 0), 2 qkv scatter
// ---------------------------------------------------------------------------
template<int MODE>
__global__ void __launch_bounds__(256, 2)
tc_gemm(const float* __restrict__ A, const float* __restrict__ B,
        const float* __restrict__ bias, float* __restrict__ C,
        int M, int N, int K)
{
    constexpr int BM = 128, BN = 128;

    __shared__ float As[2][BM][16];
    __shared__ float Bs[2][BN][16];

    const int m0 = blockIdx.y * BM;
    const int n0 = blockIdx.x * BN;
    const int tid  = threadIdx.x;
    const int lane = tid & 31;
    const int w    = tid >> 5;
    const int wm = w >> 1, wn = w & 1;
    const int g  = lane >> 2, tg = lane & 3;
    const int m0w = wm * 32, n0w = wn * 64;

    const int lrow = tid >> 2;        // 0..63 (+64)
    const int lc   = tid & 3;
    const int lkc  = lc * 4;
    const int colL = 4 * (tg ^ (g >> 1));

    float acc[2][8][4];
    #pragma unroll
    for (int i = 0; i < 2; i++)
        #pragma unroll
        for (int j = 0; j < 8; j++)
            #pragma unroll
            for (int r = 0; r < 4; r++) acc[i][j][r] = 0.f;

    for (int k0 = 0; k0 < K; k0 += 32) {
        // ---- load both subtiles
        #pragma unroll
        for (int s = 0; s < 2; s++) {
            #pragma unroll
            for (int it = 0; it < 2; it++) {
                int row = lrow + it * 64;
                int p4  = ((row >> 1) & 3);
                int gk  = k0 + s * 16 + lkc;
                int gm  = m0 + row;
                float4 v = (gm < M) ? *(const float4*)(A + (size_t)gm * K + gk)
                                    : make_float4(0.f, 0.f, 0.f, 0.f);
                As[s][row][4*(0^p4) + lc] = to_tf32(v.x);
                As[s][row][4*(1^p4) + lc] = to_tf32(v.y);
                As[s][row][4*(2^p4) + lc] = to_tf32(v.z);
                As[s][row][4*(3^p4) + lc] = to_tf32(v.w);
                int gn = n0 + row;
                float4 u = (gn < N) ? *(const float4*)(B + (size_t)gn * K + gk)
                                    : make_float4(0.f, 0.f, 0.f, 0.f);
                Bs[s][row][4*(0^p4) + lc] = to_tf32(u.x);
                Bs[s][row][4*(1^p4) + lc] = to_tf32(u.y);
                Bs[s][row][4*(2^p4) + lc] = to_tf32(u.z);
                Bs[s][row][4*(3^p4) + lc] = to_tf32(u.w);
            }
        }
        __syncthreads();

        // ---- compute both subtiles
        #pragma unroll
        for (int s = 0; s < 2; s++) {
            float4 va[4];
            #pragma unroll
            for (int i = 0; i < 4; i++)
                va[i] = *(const float4*)&As[s][m0w + g + 8*i][colL];
            float4 vb[8];
            #pragma unroll
            for (int j = 0; j < 8; j++)
                vb[j] = *(const float4*)&Bs[s][n0w + j*8 + g][colL];

            #pragma unroll
            for (int i = 0; i < 2; i++) {
                uint32_t a0[4] = {
                    __float_as_uint(va[2*i].x), __float_as_uint(va[2*i+1].x),
                    __float_as_uint(va[2*i].y), __float_as_uint(va[2*i+1].y)};
                uint32_t a8[4] = {
                    __float_as_uint(va[2*i].z), __float_as_uint(va[2*i+1].z),
                    __float_as_uint(va[2*i].w), __float_as_uint(va[2*i+1].w)};
                #pragma unroll
                for (int j = 0; j < 8; j++) {
                    uint32_t b0[2] = {__float_as_uint(vb[j].x), __float_as_uint(vb[j].y)};
                    uint32_t b8[2] = {__float_as_uint(vb[j].z), __float_as_uint(vb[j].w)};
                    mma_tf32(acc[i][j], a0, b0);
                    mma_tf32(acc[i][j], a8, b8);
                }
            }
        }
        __syncthreads();
    }

    // ---- epilogue (strength-reduced)
    #pragma unroll
    for (int i = 0; i < 2; i++) {
        #pragma unroll
        for (int rr = 0; rr < 2; rr++) {
            const int gm = m0 + m0w + i*16 + g + rr*8;
            if (gm >= M) continue;
            if (MODE == 0) {
                float* crow = C + (size_t)gm * N;
                #pragma unroll
                for (int j = 0; j < 8; j++) {
                    int gn = n0 + n0w + j*8 + tg*2;
                    crow[gn]   = acc[i][j][rr*2]   + bias[gn];
                    crow[gn+1] = acc[i][j][rr*2+1] + bias[gn+1];
                }
            } else {
                const int bb = gm / NV;
                const int nv = gm - bb * NV;
                const int qi = (nv == 0) ? 0 : (nv >= 65 ? nv - 64 : -1);
                float* kB = g_k + (size_t)bb * NH * NV * HD + (size_t)nv * HD;
                float* vB = g_v + (size_t)bb * NH * NV * HD + (size_t)nv * HD;
                float* qB = (qi >= 0)
                    ? g_q + (size_t)bb * NH * NQ * HD + (size_t)qi * HD : nullptr;
                #pragma unroll
                for (int j = 0; j < 8; j++) {
                    #pragma unroll
                    for (int e = 0; e < 2; e++) {
                        int gn = n0 + n0w + j*8 + tg*2 + e;
                        float t = acc[i][j][rr*2 + e] + bias[gn];
                        int typ = gn / DIM;
                        int hd  = gn - typ * DIM;
                        int h = hd >> 6, d = hd & 63;
                        if (typ == 1) {
                            kB[(size_t)h * NV * HD + d] = t;
                        } else if (typ == 2) {
                            vB[(size_t)h * NV * HD + d] = t;
                        } else if (qB) {
                            qB[(size_t)h * NQ * HD + d] = t;
                        }
                    }
                }
            }
        }
    }
}

// ---------------------------------------------------------------------------
// 3xTF32 GEMM + GELU (fp32-accurate hi/lo split), two subtiles per barrier.
// AMODE 0: A = given pointer (M,K), bias[gn].
// AMODE 1: A = x search rows (K=768), bias = g_tb[batch][gn].
// 64KB dynamic smem.
// ---------------------------------------------------------------------------
template<int AMODE>
__global__ void __launch_bounds__(256, 2)
tc_gemm3x_gelu(const float* __restrict__ A, const float* __restrict__ x,
               const float* __restrict__ B, int ldb,
               const float* __restrict__ bias,
               float* __restrict__ C, int M, int N, int K)
{
    constexpr int BM = 128, BN = 128;
    constexpr int TSZ = BM * 16;       // floats per subtile

    extern __shared__ float sm3[];
    float* Ah = sm3;                   // [2][128][16]
    float* Al = sm3 + 2*TSZ;
    float* Bh = sm3 + 4*TSZ;
    float* Bl = sm3 + 6*TSZ;
    #define T3(base, s, r, c) base[(s)*TSZ + (r)*16 + (c)]

    const int m0 = blockIdx.y * BM;
    const int n0 = blockIdx.x * BN;
    const int tid  = threadIdx.x;
    const int lane = tid & 31;
    const int w    = tid >> 5;
    const int wm = w >> 1, wn = w & 1;
    const int g  = lane >> 2, tg = lane & 3;
    const int m0w = wm * 32, n0w = wn * 64;

    const int lrow = tid >> 2;
    const int lc   = tid & 3;
    const int lkc  = lc * 4;
    const int colL = 4 * (tg ^ (g >> 1));

    float acc[2][8][4];
    #pragma unroll
    for (int i = 0; i < 2; i++)
        #pragma unroll
        for (int j = 0; j < 8; j++)
            #pragma unroll
            for (int r = 0; r < 4; r++) acc[i][j][r] = 0.f;

    // per-thread row base pointers (A side)
    const float* aRow[2];
    #pragma unroll
    for (int it = 0; it < 2; it++) {
        int gm = m0 + lrow + it * 64;
        if (AMODE == 1) {
            int bx = gm >> 8, sx = gm & 255;
            aRow[it] = x + ((size_t)bx * NV + 129 + sx) * DIM + lkc;
        } else {
            aRow[it] = A + (size_t)gm * K + lkc;
        }
    }

    for (int k0 = 0; k0 < K; k0 += 32) {
        #pragma unroll
        for (int s = 0; s < 2; s++) {
            #pragma unroll
            for (int it = 0; it < 2; it++) {
                int row = lrow + it * 64;
                int p4  = ((row >> 1) & 3);
                int koff = k0 + s * 16;
                float4 v = *(const float4*)(aRow[it] + koff);
                float hx = to_tf32(v.x), hy = to_tf32(v.y),
                      hz = to_tf32(v.z), hw = to_tf32(v.w);
                T3(Ah,s,row,4*(0^p4)+lc) = hx; T3(Al,s,row,4*(0^p4)+lc) = to_tf32(v.x - hx);
                T3(Ah,s,row,4*(1^p4)+lc) = hy; T3(Al,s,row,4*(1^p4)+lc) = to_tf32(v.y - hy);
                T3(Ah,s,row,4*(2^p4)+lc) = hz; T3(Al,s,row,4*(2^p4)+lc) = to_tf32(v.z - hz);
                T3(Ah,s,row,4*(3^p4)+lc) = hw; T3(Al,s,row,4*(3^p4)+lc) = to_tf32(v.w - hw);
                int gn = n0 + row;
                float4 u = (gn < N)
                    ? *(const float4*)(B + (size_t)gn * ldb + koff + lkc)
                    : make_float4(0.f, 0.f, 0.f, 0.f);
                hx = to_tf32(u.x); hy = to_tf32(u.y);
                hz = to_tf32(u.z); hw = to_tf32(u.w);
                T3(Bh,s,row,4*(0^p4)+lc) = hx; T3(Bl,s,row,4*(0^p4)+lc) = to_tf32(u.x - hx);
                T3(Bh,s,row,4*(1^p4)+lc) = hy; T3(Bl,s,row,4*(1^p4)+lc) = to_tf32(u.y - hy);
                T3(Bh,s,row,4*(2^p4)+lc) = hz; T3(Bl,s,row,4*(2^p4)+lc) = to_tf32(u.z - hz);
                T3(Bh,s,row,4*(3^p4)+lc) = hw; T3(Bl,s,row,4*(3^p4)+lc) = to_tf32(u.w - hw);
            }
        }
        __syncthreads();

        #pragma unroll
        for (int s = 0; s < 2; s++) {
            float4 vah[4], val_[4];
            #pragma unroll
            for (int i = 0; i < 4; i++) {
                int row = m0w + g + i*8;
                vah[i]  = *(const float4*)&T3(Ah,s,row,colL);
                val_[i] = *(const float4*)&T3(Al,s,row,colL);
            }
            #pragma unroll
            for (int j = 0; j < 8; j++) {
                int row = n0w + j*8 + g;
                float4 vbh = *(const float4*)&T3(Bh,s,row,colL);
                float4 vbl = *(const float4*)&T3(Bl,s,row,colL);
                uint32_t bh0[2] = {__float_as_uint(vbh.x), __float_as_uint(vbh.y)};
                uint32_t bh8[2] = {__float_as_uint(vbh.z), __float_as_uint(vbh.w)};
                uint32_t bl0[2] = {__float_as_uint(vbl.x), __float_as_uint(vbl.y)};
                uint32_t bl8[2] = {__float_as_uint(vbl.z), __float_as_uint(vbl.w)};
                #pragma unroll
                for (int i = 0; i < 2; i++) {
                    uint32_t ah0[4] = {
                        __float_as_uint(vah[2*i].x), __float_as_uint(vah[2*i+1].x),
                        __float_as_uint(vah[2*i].y), __float_as_uint(vah[2*i+1].y)};
                    uint32_t ah8[4] = {
                        __float_as_uint(vah[2*i].z), __float_as_uint(vah[2*i+1].z),
                        __float_as_uint(vah[2*i].w), __float_as_uint(vah[2*i+1].w)};
                    uint32_t al0[4] = {
                        __float_as_uint(val_[2*i].x), __float_as_uint(val_[2*i+1].x),
                        __float_as_uint(val_[2*i].y), __float_as_uint(val_[2*i+1].y)};
                    uint32_t al8[4] = {
                        __float_as_uint(val_[2*i].z), __float_as_uint(val_[2*i+1].z),
                        __float_as_uint(val_[2*i].w), __float_as_uint(val_[2*i+1].w)};
                    mma_tf32(acc[i][j], ah0, bl0);
                    mma_tf32(acc[i][j], al0, bh0);
                    mma_tf32(acc[i][j], ah0, bh0);
                    mma_tf32(acc[i][j], ah8, bl8);
                    mma_tf32(acc[i][j], al8, bh8);
                    mma_tf32(acc[i][j], ah8, bh8);
                }
            }
        }
        __syncthreads();
    }
    #undef T3

    #pragma unroll
    for (int i = 0; i < 2; i++) {
        #pragma unroll
        for (int rr = 0; rr < 2; rr++) {
            int gm = m0 + m0w + i*16 + g + rr*8;
            if (gm >= M) continue;
            float* crow = C + (size_t)gm * N;
            const float* brow = (AMODE == 1) ? g_tb + (gm >> 8) * 384 : bias;
            #pragma unroll
            for (int j = 0; j < 8; j++) {
                #pragma unroll
                for (int e = 0; e < 2; e++) {
                    int gn = n0 + n0w + j*8 + tg*2 + e;
                    if (gn >= N) continue;
                    crow[gn] = gelu_exact(acc[i][j][rr*2+e] + brow[gn]);
                }
            }
        }
    }
}

// ---------------------------------------------------------------------------
// tb[b][n] = tgt_rep[b] . W1b[n] + b1[n]
// ---------------------------------------------------------------------------
__global__ void tb_kernel(const float* __restrict__ dp1_w,
                          const float* __restrict__ dp1_b) {
    int b = blockIdx.x;
    int n = threadIdx.x;
    const float* tg = g_tgt + (size_t)b * DIM;
    const float* wr = dp1_w + (size_t)n * 1536 + DIM;
    float s = dp1_b[n];
    #pragma unroll 8
    for (int k = 0; k < DIM; k++)
        s = fmaf(tg[k], wr[k], s);
    g_tb[b * 384 + n] = s;
}

// ---------------------------------------------------------------------------
// Flash attention (unchanged from R5)
// ---------------------------------------------------------------------------
namespace {
constexpr int BQ = 128, BKV = 64;
}

struct FlashSmem {
    float Qs[HD][BQ + 4];
    float Ks[HD][BKV + 4];
    float Vs[BKV][HD + 4];
    float Ps[BKV][BQ + 4];
    int   km[BKV];
};

__global__ void __launch_bounds__(256)
flash_kernel() {
    extern __shared__ char raw_smem[];
    FlashSmem& S = *reinterpret_cast<FlashSmem*>(raw_smem);

    const int bh = blockIdx.y;
    const int b  = bh / NH, h = bh % NH;
    const int q0 = blockIdx.x * BQ;
    const int tid  = threadIdx.x;
    const int lane = tid & 31;
    const int w    = tid >> 5;
    const int g  = lane >> 2, tg = lane & 3;
    const int mw = w * 16;
    const int* db = g_db + (size_t)b * SS;

    for (int idx = tid; idx < BQ * HD; idx += 256) {
        int q = idx >> 6, d = idx & 63;
        int gq = q0 + q;
        float v = (gq < NQ) ? g_q[((size_t)bh*NQ + gq)*HD + d] * ATT_SCALE : 0.f;
        S.Qs[d][q] = to_tf32(v);
    }

    const int r0 = q0 + mw + g, r1 = r0 + 8;
    const bool qT0 = (r0 >= 1 && r0 <= 64);
    const bool qT1 = (r1 >= 1 && r1 <= 64);
    const bool qP0 = (r0 >= 65 && r0 < NQ) ? (db[r0 - 65] != 0) : false;
    const bool qP1 = (r1 >= 65 && r1 < NQ) ? (db[r1 - 65] != 0) : false;

    float m0 = -INFINITY, m1 = -INFINITY, l0 = 0.f, l1 = 0.f;
    float accO[8][4];
    #pragma unroll
    for (int j = 0; j < 8; j++)
        #pragma unroll
        for (int r = 0; r < 4; r++) accO[j][r] = 0.f;

    for (int kt = 0; kt < 7; kt++) {
        __syncthreads();
        const int kbase = kt * BKV;
        for (int idx = tid; idx < BKV * HD; idx += 256) {
            int kv = idx >> 6, d = idx & 63;
            int k = kbase + kv;
            float kvl = 0.f, vvl = 0.f;
            if (k < NV) {
                kvl = g_k[((size_t)bh*NV + k)*HD + d];
                vvl = g_v[((size_t)bh*NV + k)*HD + d];
            }
            S.Ks[d][kv] = to_tf32(kvl);
            S.Vs[kv][d] = to_tf32(vvl);
        }
        if (tid < BKV) {
            int k = kbase + tid;
            int fl = 0;
            if (k < NV) {
                fl = 4;
                if (k >= 1 && k <= 128) fl |= 1;
                if (k >= 129 && db[k - 129] != 0) fl |= 2;
            }
            S.km[tid] = fl;
        }
        __syncthreads();

        float sacc[8][4];
        #pragma unroll
        for (int j = 0; j < 8; j++)
            #pragma unroll
            for (int r = 0; r < 4; r++) sacc[j][r] = 0.f;

        #pragma unroll
        for (int kk = 0; kk < HD; kk += 8) {
            uint32_t a[4];
            a[0] = __float_as_uint(S.Qs[kk+tg  ][mw + g    ]);
            a[1] = __float_as_uint(S.Qs[kk+tg  ][mw + g + 8]);
            a[2] = __float_as_uint(S.Qs[kk+tg+4][mw + g    ]);
            a[3] = __float_as_uint(S.Qs[kk+tg+4][mw + g + 8]);
            #pragma unroll
            for (int j = 0; j < 8; j++) {
                uint32_t b2[2] = {
                    __float_as_uint(S.Ks[kk+tg  ][j*8 + g]),
                    __float_as_uint(S.Ks[kk+tg+4][j*8 + g])};
                mma_tf32(sacc[j], a, b2);
            }
        }

        int fA[8], fB[8];
        float tm0 = -INFINITY, tm1 = -INFINITY;
        #pragma unroll
        for (int j = 0; j < 8; j++) {
            int kvA = j*8 + 2*tg;
            fA[j] = S.km[kvA];
            fB[j] = S.km[kvA + 1];
            if (fA[j] & 4) { tm0 = fmaxf(tm0, sacc[j][0]); tm1 = fmaxf(tm1, sacc[j][2]); }
            if (fB[j] & 4) { tm0 = fmaxf(tm0, sacc[j][1]); tm1 = fmaxf(tm1, sacc[j][3]); }
        }
        #pragma unroll
        for (int o = 1; o <= 2; o <<= 1) {
            tm0 = fmaxf(tm0, __shfl_xor_sync(0xffffffffu, tm0, o));
            tm1 = fmaxf(tm1, __shfl_xor_sync(0xffffffffu, tm1, o));
        }
        float nm0 = fmaxf(m0, tm0), nm1 = fmaxf(m1, tm1);
        float f0 = __expf(m0 - nm0), f1 = __expf(m1 - nm1);

        float rs0 = 0.f, rs1 = 0.f;
        #pragma unroll
        for (int j = 0; j < 8; j++) {
            bool mA0 = (fA[j] & 4) && !((qT0 && (fA[j] & 2)) || (qP0 && (fA[j] & 1)));
            bool mB0 = (fB[j] & 4) && !((qT0 && (fB[j] & 2)) || (qP0 && (fB[j] & 1)));
            bool mA1 = (fA[j] & 4) && !((qT1 && (fA[j] & 2)) || (qP1 && (fA[j] & 1)));
            bool mB1 = (fB[j] & 4) && !((qT1 && (fB[j] & 2)) || (qP1 && (fB[j] & 1)));
            float e00 = mA0 ? __expf(sacc[j][0] - nm0) : 0.f;
            float e01 = mB0 ? __expf(sacc[j][1] - nm0) : 0.f;
            float e10 = mA1 ? __expf(sacc[j][2] - nm1) : 0.f;
            float e11 = mB1 ? __expf(sacc[j][3] - nm1) : 0.f;
            rs0 += e00 + e01;
            rs1 += e10 + e11;
            int kvA = j*8 + 2*tg;
            S.Ps[kvA    ][mw + g    ] = to_tf32(e00);
            S.Ps[kvA + 1][mw + g    ] = to_tf32(e01);
            S.Ps[kvA    ][mw + g + 8] = to_tf32(e10);
            S.Ps[kvA + 1][mw + g + 8] = to_tf32(e11);
        }
        #pragma unroll
        for (int o = 1; o <= 2; o <<= 1) {
            rs0 += __shfl_xor_sync(0xffffffffu, rs0, o);
            rs1 += __shfl_xor_sync(0xffffffffu, rs1, o);
        }
        l0 = l0 * f0 + rs0;
        l1 = l1 * f1 + rs1;
        #pragma unroll
        for (int j = 0; j < 8; j++) {
            accO[j][0] *= f0; accO[j][1] *= f0;
            accO[j][2] *= f1; accO[j][3] *= f1;
        }
        m0 = nm0; m1 = nm1;
        __syncwarp();

        #pragma unroll
        for (int kk = 0; kk < BKV; kk += 8) {
            uint32_t a[4];
            a[0] = __float_as_uint(S.Ps[kk+tg  ][mw + g    ]);
            a[1] = __float_as_uint(S.Ps[kk+tg  ][mw + g + 8]);
            a[2] = __float_as_uint(S.Ps[kk+tg+4][mw + g    ]);
            a[3] = __float_as_uint(S.Ps[kk+tg+4][mw + g + 8]);
            #pragma unroll
            for (int j = 0; j < 8; j++) {
                uint32_t b2[2] = {
                    __float_as_uint(S.Vs[kk+tg  ][j*8 + g]),
                    __float_as_uint(S.Vs[kk+tg+4][j*8 + g])};
                mma_tf32(accO[j], a, b2);
            }
        }
    }

    const float inv0 = 1.f / (l0 + EPS);
    const float inv1 = 1.f / (l1 + EPS);
    const float c = EPS / (float)NQ;
    #pragma unroll
    for (int j = 0; j < 8; j++) {
        #pragma unroll
        for (int r = 0; r < 4; r++) {
            int d = j*8 + 2*tg + (r & 1);
            int q = q0 + mw + g + ((r & 2) ? 8 : 0);
            if (q >= NQ) continue;
            float vs = g_vsum[bh * HD + d];
            float val = (accO[j][r] + c * vs) * ((r & 2) ? inv1 : inv0);
            g_ao[((size_t)b*NQ + q)*DIM + h*HD + d] = val;
        }
    }
}

// ---------------------------------------------------------------------------
// small kernels
// ---------------------------------------------------------------------------
__global__ void mean_kernel(const float* __restrict__ x) {
    int b = blockIdx.x;
    int c = threadIdx.x;
    float s = 0.f;
    #pragma unroll 8
    for (int t = 0; t < 64; t++)
        s += x[((size_t)b*NV + 65 + t)*DIM + c];
    g_tgt[b*DIM + c] = s * (1.0f/64.0f);
}

__global__ void mlp3_kernel(const float* __restrict__ w3,
                            const float* __restrict__ b3) {
    int gwarp = (blockIdx.x * blockDim.x + threadIdx.x) >> 5;
    int lane  = threadIdx.x & 31;
    if (gwarp >= TOKENS) return;
    const float* row = g_h2 + (size_t)gwarp * 192;
    float s0 = 0.f, s1 = 0.f;
    for (int k = lane; k < 192; k += 32) {
        float xv = row[k];
        s0 = fmaf(xv, w3[k],       s0);
        s1 = fmaf(xv, w3[192 + k], s1);
    }
    #pragma unroll
    for (int o = 16; o; o >>= 1) {
        s0 += __shfl_xor_sync(0xffffffffu, s0, o);
        s1 += __shfl_xor_sync(0xffffffffu, s1, o);
    }
    if (lane == 0)
        g_db[gwarp] = (s0 + b3[0] >= s1 + b3[1]) ? 1 : 0;
}

__global__ void vsum_kernel() {
    int bh = blockIdx.x;
    int d  = threadIdx.x;
    float s = 0.f;
    for (int k = 0; k < NV; k++)
        s += g_v[((size_t)bh*NV + k)*HD + d];
    g_vsum[bh*HD + d] = s;
}

// ---------------------------------------------------------------------------
extern "C" void kernel_launch(void* const* d_in, const int* in_sizes, int n_in,
                              void* d_out, int out_size) {
    const float* x      = (const float*)d_in[0];
    const float* qkv_w  = (const float*)d_in[2];
    const float* qkv_b  = (const float*)d_in[3];
    const float* proj_w = (const float*)d_in[4];
    const float* proj_b = (const float*)d_in[5];
    const float* dp1_w  = (const float*)d_in[6];
    const float* dp1_b  = (const float*)d_in[7];
    const float* dp2_w  = (const float*)d_in[8];
    const float* dp2_b  = (const float*)d_in[9];
    const float* dp3_w  = (const float*)d_in[10];
    const float* dp3_b  = (const float*)d_in[11];
    float* out = (float*)d_out;

    float *p_h1, *p_h2, *p_ao;
    cudaGetSymbolAddress((void**)&p_h1, g_h1);
    cudaGetSymbolAddress((void**)&p_h2, g_h2);
    cudaGetSymbolAddress((void**)&p_ao, g_ao);

    auto cdiv = [](int a, int b) { return (a + b - 1) / b; };

    constexpr int SMEM3X = 8 * 128 * 16 * 4;    // 64KB
    cudaFuncSetAttribute(tc_gemm3x_gelu<1>,
                         cudaFuncAttributeMaxDynamicSharedMemorySize, SMEM3X);
    cudaFuncSetAttribute(tc_gemm3x_gelu<0>,
                         cudaFuncAttributeMaxDynamicSharedMemorySize, SMEM3X);

    // decision path (fp32-accurate 3xTF32)
    mean_kernel<<<B_, DIM>>>(x);
    tb_kernel<<<B_, 384>>>(dp1_w, dp1_b);
    tc_gemm3x_gelu<1><<<dim3(3, 128), 256, SMEM3X>>>(
        nullptr, x, dp1_w, 1536, nullptr, p_h1, TOKENS, 384, DIM);
    tc_gemm3x_gelu<0><<<dim3(2, 128), 256, SMEM3X>>>(
        p_h1, nullptr, dp2_w, 384, dp2_b, p_h2, TOKENS, 192, 384);
    mlp3_kernel<<<cdiv(TOKENS*32, 256), 256>>>(dp3_w, dp3_b);

    // QKV projection + head scatter
    tc_gemm<2><<<dim3(cdiv(QKVD,128), cdiv(B_*NV,128)), 256>>>(
        x, qkv_w, qkv_b, nullptr, B_*NV, QKVD, DIM);

    // V column sums (for eps/NQ term)
    vsum_kernel<<<BH, HD>>>();

    // fused attention
    constexpr size_t FLASH_SMEM = sizeof(FlashSmem);
    cudaFuncSetAttribute(flash_kernel,
                         cudaFuncAttributeMaxDynamicSharedMemorySize,
                         (int)FLASH_SMEM);
    flash_kernel<<<dim3(cdiv(NQ, BQ), BH), 256, FLASH_SMEM>>>();

    // output projection
    tc_gemm<0><<<dim3(cdiv(DIM,128), cdiv(B_*NQ,128)), 256>>>(
        p_ao, proj_w, proj_b, out, B_*NQ, DIM, DIM);
}

// round 7
// speedup vs baseline: 2.8218x; 1.0956x over previous
#include <cuda_runtime.h>
#include <math.h>
#include <stdint.h>

namespace {
constexpr int B_   = 64;
constexpr int NV   = 385;
constexpr int NQ   = 321;
constexpr int SS   = 256;
constexpr int NH   = 12;
constexpr int HD   = 64;
constexpr int DIM  = 768;
constexpr int QKVD = 2304;
constexpr int BH   = B_ * NH;
constexpr int TOKENS = B_ * SS;
constexpr float ATT_SCALE = 0.125f;
constexpr float EPS = 1e-6f;
}

__device__ float g_tgt[B_ * DIM];
__device__ float g_tb[B_ * 384];
__device__ float g_h1[(size_t)TOKENS * 384];
__device__ float g_h2[(size_t)TOKENS * 192];
__device__ int   g_db[TOKENS];
__device__ float g_q [(size_t)BH * NQ * HD];
__device__ float g_k [(size_t)BH * NV * HD];
__device__ float g_v [(size_t)BH * NV * HD];
__device__ float g_vsum[BH * HD];
__device__ float g_ao[(size_t)B_ * NQ * DIM];
// pre-rounded + k-transposed operands for the async GEMMs
__device__ float g_xt [(size_t)B_ * NV * DIM];
__device__ float g_qwt[(size_t)QKVD * DIM];
__device__ float g_pwt[(size_t)DIM * DIM];

__device__ __forceinline__ float gelu_exact(float x) {
    return 0.5f * x * (1.0f + erff(x * 0.70710678118654752440f));
}

__device__ __forceinline__ float to_tf32(float x) {
    uint32_t r;
    asm("cvt.rna.tf32.f32 %0, %1;" : "=r"(r) : "f"(x));
    return __uint_as_float(r);
}

__device__ __forceinline__ void mma_tf32(float c[4], const uint32_t a[4],
                                         const uint32_t b[2]) {
    asm volatile(
        "mma.sync.aligned.m16n8k8.row.col.f32.tf32.tf32.f32 "
        "{%0,%1,%2,%3}, {%4,%5,%6,%7}, {%8,%9}, {%0,%1,%2,%3};"
        : "+f"(c[0]), "+f"(c[1]), "+f"(c[2]), "+f"(c[3])
        : "r"(a[0]), "r"(a[1]), "r"(a[2]), "r"(a[3]),
          "r"(b[0]), "r"(b[1]));
}

__device__ __forceinline__ uint32_t smem_u32(const void* p) {
    return (uint32_t)__cvta_generic_to_shared(p);
}
__device__ __forceinline__ void cp_async16(uint32_t dst, const void* src, int src_size) {
    asm volatile("cp.async.cg.shared.global [%0], [%1], 16, %2;"
                 :: "r"(dst), "l"(src), "r"(src_size));
}
#define CP_COMMIT() asm volatile("cp.async.commit_group;")
#define CP_WAIT1()  asm volatile("cp.async.wait_group 1;")

// ---------------------------------------------------------------------------
// Pre-pass: tf32-round and k-transpose within 16-element groups:
//   out[16g + 4*(k&3) + (k>>2)] = tf32(in[16g + k])
// so one 16B unit = one MMA fragment (k, k+4, k+8, k+12).
// ---------------------------------------------------------------------------
__global__ void xform_kernel(const float* __restrict__ in,
                             float* __restrict__ out, long long ngroups) {
    long long i = blockIdx.x * (long long)blockDim.x + threadIdx.x;
    if (i >= ngroups) return;
    const float4* ip = (const float4*)(in + i * 16);
    float4 a0 = ip[0], a1 = ip[1], a2 = ip[2], a3 = ip[3];
    float4* op = (float4*)(out + i * 16);
    op[0] = make_float4(to_tf32(a0.x), to_tf32(a1.x), to_tf32(a2.x), to_tf32(a3.x));
    op[1] = make_float4(to_tf32(a0.y), to_tf32(a1.y), to_tf32(a2.y), to_tf32(a3.y));
    op[2] = make_float4(to_tf32(a0.z), to_tf32(a1.z), to_tf32(a2.z), to_tf32(a3.z));
    op[3] = make_float4(to_tf32(a0.w), to_tf32(a1.w), to_tf32(a2.w), to_tf32(a3.w));
}

// ---------------------------------------------------------------------------
// cp.async double-buffered TF32 GEMM. A (M,K) and B (N,K) are pre-rounded and
// k-transposed (xform layout). K % 32 == 0, N % 128 == 0 for MODE 0.
// smem: 2 stages x (A 128x32 + B 128x32) floats = 64 KB dynamic.
// Unit swizzle: physical unit = u ^ (((row&1)<<2) | (row&3)) — conflict-free
// for both cp.async stores and fragment LDS.128 loads.
// MODE: 0 bias+store, 2 qkv scatter
// ---------------------------------------------------------------------------
template<int MODE>
__global__ void __launch_bounds__(256, 2)
tc_gemm_async(const float* __restrict__ A, const float* __restrict__ B,
              const float* __restrict__ bias, float* __restrict__ C,
              int M, int N, int K)
{
    extern __shared__ float smx[];          // [2][2][128][32]

    const int m0 = blockIdx.y * 128;
    const int n0 = blockIdx.x * 128;
    const int tid  = threadIdx.x;
    const int lane = tid & 31;
    const int w    = tid >> 5;
    const int wm = w >> 1, wn = w & 1;
    const int g  = lane >> 2, tg = lane & 3;
    const int m0w = wm * 32, n0w = wn * 64;

    // copy thread coords: 4 A units + 4 B units per 32-k tile
    const int crow = tid >> 3;              // 0..31 (+32 per i)
    const int cu   = tid & 7;

    // fragment swizzle (row bits constant across fragment rows: row ≡ g mod 8)
    const int fswz = ((g & 1) << 2) | (g & 3);

    float acc[2][8][4];
    #pragma unroll
    for (int i = 0; i < 2; i++)
        #pragma unroll
        for (int j = 0; j < 8; j++)
            #pragma unroll
            for (int r = 0; r < 4; r++) acc[i][j][r] = 0.f;

    auto issue = [&](int k0, int st) {
        float* sa = smx + st * 8192;
        float* sb = sa + 4096;
        #pragma unroll
        for (int i = 0; i < 4; i++) {
            int row = crow + 32 * i;
            int pu  = cu ^ (((row & 1) << 2) | (row & 3));
            int gm  = m0 + row;
            int gmc = gm < M ? gm : M - 1;
            cp_async16(smem_u32(sa + row * 32 + pu * 4),
                       A + (size_t)gmc * K + k0 + cu * 4, gm < M ? 16 : 0);
            int gn  = n0 + row;
            int gnc = gn < N ? gn : N - 1;
            cp_async16(smem_u32(sb + row * 32 + pu * 4),
                       B + (size_t)gnc * K + k0 + cu * 4, gn < N ? 16 : 0);
        }
        CP_COMMIT();
    };

    const int T = K / 32;
    issue(0, 0);
    for (int t = 0; t < T; t++) {
        if (t + 1 < T) issue((t + 1) * 32, (t + 1) & 1);
        else           CP_COMMIT();         // empty group keeps wait count valid
        CP_WAIT1();
        __syncthreads();

        const float* sa = smx + (t & 1) * 8192;
        const float* sb = sa + 4096;
        #pragma unroll
        for (int gq = 0; gq < 2; gq++) {
            const int pu4 = ((4 * gq + tg) ^ fswz) * 4;
            float4 va[4];
            #pragma unroll
            for (int i = 0; i < 4; i++)
                va[i] = *(const float4*)(sa + (m0w + g + 8*i) * 32 + pu4);
            float4 vb[8];
            #pragma unroll
            for (int j = 0; j < 8; j++)
                vb[j] = *(const float4*)(sb + (n0w + 8*j + g) * 32 + pu4);

            #pragma unroll
            for (int i = 0; i < 2; i++) {
                uint32_t a0[4] = {
                    __float_as_uint(va[2*i].x), __float_as_uint(va[2*i+1].x),
                    __float_as_uint(va[2*i].y), __float_as_uint(va[2*i+1].y)};
                uint32_t a8[4] = {
                    __float_as_uint(va[2*i].z), __float_as_uint(va[2*i+1].z),
                    __float_as_uint(va[2*i].w), __float_as_uint(va[2*i+1].w)};
                #pragma unroll
                for (int j = 0; j < 8; j++) {
                    uint32_t b0[2] = {__float_as_uint(vb[j].x), __float_as_uint(vb[j].y)};
                    uint32_t b8[2] = {__float_as_uint(vb[j].z), __float_as_uint(vb[j].w)};
                    mma_tf32(acc[i][j], a0, b0);
                    mma_tf32(acc[i][j], a8, b8);
                }
            }
        }
        __syncthreads();
    }

    // ---- epilogue
    #pragma unroll
    for (int i = 0; i < 2; i++) {
        #pragma unroll
        for (int rr = 0; rr < 2; rr++) {
            const int gm = m0 + m0w + i*16 + g + rr*8;
            if (gm >= M) continue;
            if (MODE == 0) {
                float* crowp = C + (size_t)gm * N;
                #pragma unroll
                for (int j = 0; j < 8; j++) {
                    int gn = n0 + n0w + j*8 + tg*2;
                    crowp[gn]   = acc[i][j][rr*2]   + bias[gn];
                    crowp[gn+1] = acc[i][j][rr*2+1] + bias[gn+1];
                }
            } else {
                const int bb = gm / NV;
                const int nv = gm - bb * NV;
                const int qi = (nv == 0) ? 0 : (nv >= 65 ? nv - 64 : -1);
                float* kB = g_k + (size_t)bb * NH * NV * HD + (size_t)nv * HD;
                float* vB = g_v + (size_t)bb * NH * NV * HD + (size_t)nv * HD;
                float* qB = (qi >= 0)
                    ? g_q + (size_t)bb * NH * NQ * HD + (size_t)qi * HD : nullptr;
                #pragma unroll
                for (int j = 0; j < 8; j++) {
                    #pragma unroll
                    for (int e = 0; e < 2; e++) {
                        int gn = n0 + n0w + j*8 + tg*2 + e;
                        float t = acc[i][j][rr*2 + e] + bias[gn];
                        int typ = gn / DIM;
                        int hd  = gn - typ * DIM;
                        int h = hd >> 6, d = hd & 63;
                        if (typ == 1) {
                            kB[(size_t)h * NV * HD + d] = t;
                        } else if (typ == 2) {
                            vB[(size_t)h * NV * HD + d] = t;
                        } else if (qB) {
                            qB[(size_t)h * NQ * HD + d] = t;
                        }
                    }
                }
            }
        }
    }
}

// ---------------------------------------------------------------------------
// 3xTF32 GEMM + GELU (fp32-accurate hi/lo split) — unchanged from R6.
// ---------------------------------------------------------------------------
template<int AMODE>
__global__ void __launch_bounds__(256, 2)
tc_gemm3x_gelu(const float* __restrict__ A, const float* __restrict__ x,
               const float* __restrict__ B, int ldb,
               const float* __restrict__ bias,
               float* __restrict__ C, int M, int N, int K)
{
    constexpr int BM = 128;
    constexpr int TSZ = BM * 16;

    extern __shared__ float sm3[];
    float* Ah = sm3;
    float* Al = sm3 + 2*TSZ;
    float* Bh = sm3 + 4*TSZ;
    float* Bl = sm3 + 6*TSZ;
    #define T3(base, s, r, c) base[(s)*TSZ + (r)*16 + (c)]

    const int m0 = blockIdx.y * BM;
    const int n0 = blockIdx.x * 128;
    const int tid  = threadIdx.x;
    const int lane = tid & 31;
    const int w    = tid >> 5;
    const int wm = w >> 1, wn = w & 1;
    const int g  = lane >> 2, tg = lane & 3;
    const int m0w = wm * 32, n0w = wn * 64;

    const int lrow = tid >> 2;
    const int lc   = tid & 3;
    const int lkc  = lc * 4;
    const int colL = 4 * (tg ^ (g >> 1));

    float acc[2][8][4];
    #pragma unroll
    for (int i = 0; i < 2; i++)
        #pragma unroll
        for (int j = 0; j < 8; j++)
            #pragma unroll
            for (int r = 0; r < 4; r++) acc[i][j][r] = 0.f;

    const float* aRow[2];
    #pragma unroll
    for (int it = 0; it < 2; it++) {
        int gm = m0 + lrow + it * 64;
        if (AMODE == 1) {
            int bx = gm >> 8, sx = gm & 255;
            aRow[it] = x + ((size_t)bx * NV + 129 + sx) * DIM + lkc;
        } else {
            aRow[it] = A + (size_t)gm * K + lkc;
        }
    }

    for (int k0 = 0; k0 < K; k0 += 32) {
        #pragma unroll
        for (int s = 0; s < 2; s++) {
            #pragma unroll
            for (int it = 0; it < 2; it++) {
                int row = lrow + it * 64;
                int p4  = ((row >> 1) & 3);
                int koff = k0 + s * 16;
                float4 v = *(const float4*)(aRow[it] + koff);
                float hx = to_tf32(v.x), hy = to_tf32(v.y),
                      hz = to_tf32(v.z), hw = to_tf32(v.w);
                T3(Ah,s,row,4*(0^p4)+lc) = hx; T3(Al,s,row,4*(0^p4)+lc) = to_tf32(v.x - hx);
                T3(Ah,s,row,4*(1^p4)+lc) = hy; T3(Al,s,row,4*(1^p4)+lc) = to_tf32(v.y - hy);
                T3(Ah,s,row,4*(2^p4)+lc) = hz; T3(Al,s,row,4*(2^p4)+lc) = to_tf32(v.z - hz);
                T3(Ah,s,row,4*(3^p4)+lc) = hw; T3(Al,s,row,4*(3^p4)+lc) = to_tf32(v.w - hw);
                int gn = n0 + row;
                float4 u = (gn < N)
                    ? *(const float4*)(B + (size_t)gn * ldb + koff + lkc)
                    : make_float4(0.f, 0.f, 0.f, 0.f);
                hx = to_tf32(u.x); hy = to_tf32(u.y);
                hz = to_tf32(u.z); hw = to_tf32(u.w);
                T3(Bh,s,row,4*(0^p4)+lc) = hx; T3(Bl,s,row,4*(0^p4)+lc) = to_tf32(u.x - hx);
                T3(Bh,s,row,4*(1^p4)+lc) = hy; T3(Bl,s,row,4*(1^p4)+lc) = to_tf32(u.y - hy);
                T3(Bh,s,row,4*(2^p4)+lc) = hz; T3(Bl,s,row,4*(2^p4)+lc) = to_tf32(u.z - hz);
                T3(Bh,s,row,4*(3^p4)+lc) = hw; T3(Bl,s,row,4*(3^p4)+lc) = to_tf32(u.w - hw);
            }
        }
        __syncthreads();

        #pragma unroll
        for (int s = 0; s < 2; s++) {
            float4 vah[4], val_[4];
            #pragma unroll
            for (int i = 0; i < 4; i++) {
                int row = m0w + g + i*8;
                vah[i]  = *(const float4*)&T3(Ah,s,row,colL);
                val_[i] = *(const float4*)&T3(Al,s,row,colL);
            }
            #pragma unroll
            for (int j = 0; j < 8; j++) {
                int row = n0w + j*8 + g;
                float4 vbh = *(const float4*)&T3(Bh,s,row,colL);
                float4 vbl = *(const float4*)&T3(Bl,s,row,colL);
                uint32_t bh0[2] = {__float_as_uint(vbh.x), __float_as_uint(vbh.y)};
                uint32_t bh8[2] = {__float_as_uint(vbh.z), __float_as_uint(vbh.w)};
                uint32_t bl0[2] = {__float_as_uint(vbl.x), __float_as_uint(vbl.y)};
                uint32_t bl8[2] = {__float_as_uint(vbl.z), __float_as_uint(vbl.w)};
                #pragma unroll
                for (int i = 0; i < 2; i++) {
                    uint32_t ah0[4] = {
                        __float_as_uint(vah[2*i].x), __float_as_uint(vah[2*i+1].x),
                        __float_as_uint(vah[2*i].y), __float_as_uint(vah[2*i+1].y)};
                    uint32_t ah8[4] = {
                        __float_as_uint(vah[2*i].z), __float_as_uint(vah[2*i+1].z),
                        __float_as_uint(vah[2*i].w), __float_as_uint(vah[2*i+1].w)};
                    uint32_t al0[4] = {
                        __float_as_uint(val_[2*i].x), __float_as_uint(val_[2*i+1].x),
                        __float_as_uint(val_[2*i].y), __float_as_uint(val_[2*i+1].y)};
                    uint32_t al8[4] = {
                        __float_as_uint(val_[2*i].z), __float_as_uint(val_[2*i+1].z),
                        __float_as_uint(val_[2*i].w), __float_as_uint(val_[2*i+1].w)};
                    mma_tf32(acc[i][j], ah0, bl0);
                    mma_tf32(acc[i][j], al0, bh0);
                    mma_tf32(acc[i][j], ah0, bh0);
                    mma_tf32(acc[i][j], ah8, bl8);
                    mma_tf32(acc[i][j], al8, bh8);
                    mma_tf32(acc[i][j], ah8, bh8);
                }
            }
        }
        __syncthreads();
    }
    #undef T3

    #pragma unroll
    for (int i = 0; i < 2; i++) {
        #pragma unroll
        for (int rr = 0; rr < 2; rr++) {
            int gm = m0 + m0w + i*16 + g + rr*8;
            if (gm >= M) continue;
            float* crowp = C + (size_t)gm * N;
            const float* brow = (AMODE == 1) ? g_tb + (gm >> 8) * 384 : bias;
            #pragma unroll
            for (int j = 0; j < 8; j++) {
                #pragma unroll
                for (int e = 0; e < 2; e++) {
                    int gn = n0 + n0w + j*8 + tg*2 + e;
                    if (gn >= N) continue;
                    crowp[gn] = gelu_exact(acc[i][j][rr*2+e] + brow[gn]);
                }
            }
        }
    }
}

// ---------------------------------------------------------------------------
__global__ void tb_kernel(const float* __restrict__ dp1_w,
                          const float* __restrict__ dp1_b) {
    int b = blockIdx.x;
    int n = threadIdx.x;
    const float* tg = g_tgt + (size_t)b * DIM;
    const float* wr = dp1_w + (size_t)n * 1536 + DIM;
    float s = dp1_b[n];
    #pragma unroll 8
    for (int k = 0; k < DIM; k++)
        s = fmaf(tg[k], wr[k], s);
    g_tb[b * 384 + n] = s;
}

// ---------------------------------------------------------------------------
// Flash attention; epilogue now writes g_ao tf32-rounded + k-transposed.
// ---------------------------------------------------------------------------
namespace {
constexpr int BQ = 128, BKV = 64;
}

struct FlashSmem {
    float Qs[HD][BQ + 4];
    float Ks[HD][BKV + 4];
    float Vs[BKV][HD + 4];
    float Ps[BKV][BQ + 4];
    int   km[BKV];
};

__global__ void __launch_bounds__(256)
flash_kernel() {
    extern __shared__ char raw_smem[];
    FlashSmem& S = *reinterpret_cast<FlashSmem*>(raw_smem);

    const int bh = blockIdx.y;
    const int b  = bh / NH, h = bh % NH;
    const int q0 = blockIdx.x * BQ;
    const int tid  = threadIdx.x;
    const int lane = tid & 31;
    const int w    = tid >> 5;
    const int g  = lane >> 2, tg = lane & 3;
    const int mw = w * 16;
    const int* db = g_db + (size_t)b * SS;

    for (int idx = tid; idx < BQ * HD; idx += 256) {
        int q = idx >> 6, d = idx & 63;
        int gq = q0 + q;
        float v = (gq < NQ) ? g_q[((size_t)bh*NQ + gq)*HD + d] * ATT_SCALE : 0.f;
        S.Qs[d][q] = to_tf32(v);
    }

    const int r0 = q0 + mw + g, r1 = r0 + 8;
    const bool qT0 = (r0 >= 1 && r0 <= 64);
    const bool qT1 = (r1 >= 1 && r1 <= 64);
    const bool qP0 = (r0 >= 65 && r0 < NQ) ? (db[r0 - 65] != 0) : false;
    const bool qP1 = (r1 >= 65 && r1 < NQ) ? (db[r1 - 65] != 0) : false;

    float m0 = -INFINITY, m1 = -INFINITY, l0 = 0.f, l1 = 0.f;
    float accO[8][4];
    #pragma unroll
    for (int j = 0; j < 8; j++)
        #pragma unroll
        for (int r = 0; r < 4; r++) accO[j][r] = 0.f;

    for (int kt = 0; kt < 7; kt++) {
        __syncthreads();
        const int kbase = kt * BKV;
        for (int idx = tid; idx < BKV * HD; idx += 256) {
            int kv = idx >> 6, d = idx & 63;
            int k = kbase + kv;
            float kvl = 0.f, vvl = 0.f;
            if (k < NV) {
                kvl = g_k[((size_t)bh*NV + k)*HD + d];
                vvl = g_v[((size_t)bh*NV + k)*HD + d];
            }
            S.Ks[d][kv] = to_tf32(kvl);
            S.Vs[kv][d] = to_tf32(vvl);
        }
        if (tid < BKV) {
            int k = kbase + tid;
            int fl = 0;
            if (k < NV) {
                fl = 4;
                if (k >= 1 && k <= 128) fl |= 1;
                if (k >= 129 && db[k - 129] != 0) fl |= 2;
            }
            S.km[tid] = fl;
        }
        __syncthreads();

        float sacc[8][4];
        #pragma unroll
        for (int j = 0; j < 8; j++)
            #pragma unroll
            for (int r = 0; r < 4; r++) sacc[j][r] = 0.f;

        #pragma unroll
        for (int kk = 0; kk < HD; kk += 8) {
            uint32_t a[4];
            a[0] = __float_as_uint(S.Qs[kk+tg  ][mw + g    ]);
            a[1] = __float_as_uint(S.Qs[kk+tg  ][mw + g + 8]);
            a[2] = __float_as_uint(S.Qs[kk+tg+4][mw + g    ]);
            a[3] = __float_as_uint(S.Qs[kk+tg+4][mw + g + 8]);
            #pragma unroll
            for (int j = 0; j < 8; j++) {
                uint32_t b2[2] = {
                    __float_as_uint(S.Ks[kk+tg  ][j*8 + g]),
                    __float_as_uint(S.Ks[kk+tg+4][j*8 + g])};
                mma_tf32(sacc[j], a, b2);
            }
        }

        int fA[8], fB[8];
        float tm0 = -INFINITY, tm1 = -INFINITY;
        #pragma unroll
        for (int j = 0; j < 8; j++) {
            int kvA = j*8 + 2*tg;
            fA[j] = S.km[kvA];
            fB[j] = S.km[kvA + 1];
            if (fA[j] & 4) { tm0 = fmaxf(tm0, sacc[j][0]); tm1 = fmaxf(tm1, sacc[j][2]); }
            if (fB[j] & 4) { tm0 = fmaxf(tm0, sacc[j][1]); tm1 = fmaxf(tm1, sacc[j][3]); }
        }
        #pragma unroll
        for (int o = 1; o <= 2; o <<= 1) {
            tm0 = fmaxf(tm0, __shfl_xor_sync(0xffffffffu, tm0, o));
            tm1 = fmaxf(tm1, __shfl_xor_sync(0xffffffffu, tm1, o));
        }
        float nm0 = fmaxf(m0, tm0), nm1 = fmaxf(m1, tm1);
        float f0 = __expf(m0 - nm0), f1 = __expf(m1 - nm1);

        float rs0 = 0.f, rs1 = 0.f;
        #pragma unroll
        for (int j = 0; j < 8; j++) {
            bool mA0 = (fA[j] & 4) && !((qT0 && (fA[j] & 2)) || (qP0 && (fA[j] & 1)));
            bool mB0 = (fB[j] & 4) && !((qT0 && (fB[j] & 2)) || (qP0 && (fB[j] & 1)));
            bool mA1 = (fA[j] & 4) && !((qT1 && (fA[j] & 2)) || (qP1 && (fA[j] & 1)));
            bool mB1 = (fB[j] & 4) && !((qT1 && (fB[j] & 2)) || (qP1 && (fB[j] & 1)));
            float e00 = mA0 ? __expf(sacc[j][0] - nm0) : 0.f;
            float e01 = mB0 ? __expf(sacc[j][1] - nm0) : 0.f;
            float e10 = mA1 ? __expf(sacc[j][2] - nm1) : 0.f;
            float e11 = mB1 ? __expf(sacc[j][3] - nm1) : 0.f;
            rs0 += e00 + e01;
            rs1 += e10 + e11;
            int kvA = j*8 + 2*tg;
            S.Ps[kvA    ][mw + g    ] = to_tf32(e00);
            S.Ps[kvA + 1][mw + g    ] = to_tf32(e01);
            S.Ps[kvA    ][mw + g + 8] = to_tf32(e10);
            S.Ps[kvA + 1][mw + g + 8] = to_tf32(e11);
        }
        #pragma unroll
        for (int o = 1; o <= 2; o <<= 1) {
            rs0 += __shfl_xor_sync(0xffffffffu, rs0, o);
            rs1 += __shfl_xor_sync(0xffffffffu, rs1, o);
        }
        l0 = l0 * f0 + rs0;
        l1 = l1 * f1 + rs1;
        #pragma unroll
        for (int j = 0; j < 8; j++) {
            accO[j][0] *= f0; accO[j][1] *= f0;
            accO[j][2] *= f1; accO[j][3] *= f1;
        }
        m0 = nm0; m1 = nm1;
        __syncwarp();

        #pragma unroll
        for (int kk = 0; kk < BKV; kk += 8) {
            uint32_t a[4];
            a[0] = __float_as_uint(S.Ps[kk+tg  ][mw + g    ]);
            a[1] = __float_as_uint(S.Ps[kk+tg  ][mw + g + 8]);
            a[2] = __float_as_uint(S.Ps[kk+tg+4][mw + g    ]);
            a[3] = __float_as_uint(S.Ps[kk+tg+4][mw + g + 8]);
            #pragma unroll
            for (int j = 0; j < 8; j++) {
                uint32_t b2[2] = {
                    __float_as_uint(S.Vs[kk+tg  ][j*8 + g]),
                    __float_as_uint(S.Vs[kk+tg+4][j*8 + g])};
                mma_tf32(accO[j], a, b2);
            }
        }
    }

    const float inv0 = 1.f / (l0 + EPS);
    const float inv1 = 1.f / (l1 + EPS);
    const float c = EPS / (float)NQ;
    #pragma unroll
    for (int j = 0; j < 8; j++) {
        #pragma unroll
        for (int r = 0; r < 4; r++) {
            int d = j*8 + 2*tg + (r & 1);
            int q = q0 + mw + g + ((r & 2) ? 8 : 0);
            if (q >= NQ) continue;
            float vs = g_vsum[bh * HD + d];
            float val = (accO[j][r] + c * vs) * ((r & 2) ? inv1 : inv0);
            // xform layout: transpose within 16-group + tf32 round
            int dt = (d & ~15) | ((d & 3) << 2) | ((d >> 2) & 3);
            g_ao[((size_t)b*NQ + q)*DIM + h*HD + dt] = to_tf32(val);
        }
    }
}

// ---------------------------------------------------------------------------
__global__ void mean_kernel(const float* __restrict__ x) {
    int b = blockIdx.x;
    int c = threadIdx.x;
    float s = 0.f;
    #pragma unroll 8
    for (int t = 0; t < 64; t++)
        s += x[((size_t)b*NV + 65 + t)*DIM + c];
    g_tgt[b*DIM + c] = s * (1.0f/64.0f);
}

__global__ void mlp3_kernel(const float* __restrict__ w3,
                            const float* __restrict__ b3) {
    int gwarp = (blockIdx.x * blockDim.x + threadIdx.x) >> 5;
    int lane  = threadIdx.x & 31;
    if (gwarp >= TOKENS) return;
    const float* row = g_h2 + (size_t)gwarp * 192;
    float s0 = 0.f, s1 = 0.f;
    for (int k = lane; k < 192; k += 32) {
        float xv = row[k];
        s0 = fmaf(xv, w3[k],       s0);
        s1 = fmaf(xv, w3[192 + k], s1);
    }
    #pragma unroll
    for (int o = 16; o; o >>= 1) {
        s0 += __shfl_xor_sync(0xffffffffu, s0, o);
        s1 += __shfl_xor_sync(0xffffffffu, s1, o);
    }
    if (lane == 0)
        g_db[gwarp] = (s0 + b3[0] >= s1 + b3[1]) ? 1 : 0;
}

__global__ void vsum_kernel() {
    int bh = blockIdx.x;
    int d  = threadIdx.x;
    float s = 0.f;
    for (int k = 0; k < NV; k++)
        s += g_v[((size_t)bh*NV + k)*HD + d];
    g_vsum[bh*HD + d] = s;
}

// ---------------------------------------------------------------------------
extern "C" void kernel_launch(void* const* d_in, const int* in_sizes, int n_in,
                              void* d_out, int out_size) {
    const float* x      = (const float*)d_in[0];
    const float* qkv_w  = (const float*)d_in[2];
    const float* qkv_b  = (const float*)d_in[3];
    const float* proj_w = (const float*)d_in[4];
    const float* proj_b = (const float*)d_in[5];
    const float* dp1_w  = (const float*)d_in[6];
    const float* dp1_b  = (const float*)d_in[7];
    const float* dp2_w  = (const float*)d_in[8];
    const float* dp2_b  = (const float*)d_in[9];
    const float* dp3_w  = (const float*)d_in[10];
    const float* dp3_b  = (const float*)d_in[11];
    float* out = (float*)d_out;

    float *p_h1, *p_h2, *p_ao, *p_xt, *p_qwt, *p_pwt;
    cudaGetSymbolAddress((void**)&p_h1,  g_h1);
    cudaGetSymbolAddress((void**)&p_h2,  g_h2);
    cudaGetSymbolAddress((void**)&p_ao,  g_ao);
    cudaGetSymbolAddress((void**)&p_xt,  g_xt);
    cudaGetSymbolAddress((void**)&p_qwt, g_qwt);
    cudaGetSymbolAddress((void**)&p_pwt, g_pwt);

    auto cdiv = [](int a, int b) { return (a + b - 1) / b; };

    constexpr int SMEM3X = 8 * 128 * 16 * 4;       // 64KB
    constexpr int SMEMAS = 2 * 2 * 128 * 32 * 4;   // 64KB
    cudaFuncSetAttribute(tc_gemm3x_gelu<1>,
                         cudaFuncAttributeMaxDynamicSharedMemorySize, SMEM3X);
    cudaFuncSetAttribute(tc_gemm3x_gelu<0>,
                         cudaFuncAttributeMaxDynamicSharedMemorySize, SMEM3X);
    cudaFuncSetAttribute(tc_gemm_async<2>,
                         cudaFuncAttributeMaxDynamicSharedMemorySize, SMEMAS);
    cudaFuncSetAttribute(tc_gemm_async<0>,
                         cudaFuncAttributeMaxDynamicSharedMemorySize, SMEMAS);

    // pre-round + k-transpose operands for async GEMMs
    {
        long long gx = (long long)B_ * NV * (DIM / 16);
        xform_kernel<<<(unsigned)cdiv((int)gx, 256), 256>>>(x, p_xt, gx);
        long long gw = (long long)QKVD * (DIM / 16);
        xform_kernel<<<(unsigned)cdiv((int)gw, 256), 256>>>(qkv_w, p_qwt, gw);
        long long gp = (long long)DIM * (DIM / 16);
        xform_kernel<<<(unsigned)cdiv((int)gp, 256), 256>>>(proj_w, p_pwt, gp);
    }

    // decision path (fp32-accurate 3xTF32)
    mean_kernel<<<B_, DIM>>>(x);
    tb_kernel<<<B_, 384>>>(dp1_w, dp1_b);
    tc_gemm3x_gelu<1><<<dim3(3, 128), 256, SMEM3X>>>(
        nullptr, x, dp1_w, 1536, nullptr, p_h1, TOKENS, 384, DIM);
    tc_gemm3x_gelu<0><<<dim3(2, 128), 256, SMEM3X>>>(
        p_h1, nullptr, dp2_w, 384, dp2_b, p_h2, TOKENS, 192, 384);
    mlp3_kernel<<<cdiv(TOKENS*32, 256), 256>>>(dp3_w, dp3_b);

    // QKV projection + head scatter (async pipeline)
    tc_gemm_async<2><<<dim3(QKVD/128, cdiv(B_*NV,128)), 256, SMEMAS>>>(
        p_xt, p_qwt, qkv_b, nullptr, B_*NV, QKVD, DIM);

    // V column sums
    vsum_kernel<<<BH, HD>>>();

    // fused attention
    constexpr size_t FLASH_SMEM = sizeof(FlashSmem);
    cudaFuncSetAttribute(flash_kernel,
                         cudaFuncAttributeMaxDynamicSharedMemorySize,
                         (int)FLASH_SMEM);
    flash_kernel<<<dim3(cdiv(NQ, BQ), BH), 256, FLASH_SMEM>>>();

    // output projection (async pipeline)
    tc_gemm_async<0><<<dim3(DIM/128, cdiv(B_*NQ,128)), 256, SMEMAS>>>(
        p_ao, p_pwt, proj_b, out, B_*NQ, DIM, DIM);
}